// round 11
// baseline (speedup 1.0000x reference)
#include <cuda_runtime.h>
#include <cuda_bf16.h>
#include <stdint.h>

// Shapes fixed by the problem: b=4, l=2048, d_model=1024, h=8, dk=128.
#define B_  4
#define L_  2048
#define D_  1024
#define H_  8
#define DK_ 128

// Pre-split inputs/weights (hi + residual lo bf16).
__device__ __nv_bfloat16 g_Xh[3 * B_ * L_ * D_];   // k/q/v inputs, [pj][b][t][d]
__device__ __nv_bfloat16 g_Xl[3 * B_ * L_ * D_];
__device__ __nv_bfloat16 g_Wh[4 * D_ * D_];        // Wk,Wq,Wv,Wu, [pj][c][d]
__device__ __nv_bfloat16 g_Wl[4 * D_ * D_];

// Projections, split bf16, channel-major Y[b][c][t]. Yq/Yv carry dk^-.5*log2e.
__device__ __nv_bfloat16 g_Ykh[B_ * D_ * L_];
__device__ __nv_bfloat16 g_Ykl[B_ * D_ * L_];
__device__ __nv_bfloat16 g_Yqh[B_ * D_ * L_];
__device__ __nv_bfloat16 g_Yql[B_ * D_ * L_];
__device__ __nv_bfloat16 g_Yvh[B_ * D_ * L_];
__device__ __nv_bfloat16 g_Yvl[B_ * D_ * L_];

// Attention outputs (fp32) and their summed split-bf16 form.
__device__ float g_Z1[B_ * L_ * D_];
__device__ float g_Z2[B_ * L_ * D_];
__device__ __nv_bfloat16 g_Zh[B_ * L_ * D_];
__device__ __nv_bfloat16 g_Zl[B_ * L_ * D_];

// ---------------------------------------------------------------------------
// Helpers
// ---------------------------------------------------------------------------
__device__ __forceinline__ uint32_t sptr(const void* p) {
  return (uint32_t)__cvta_generic_to_shared(p);
}

__device__ __forceinline__ void ldsm4(uint32_t r[4], uint32_t a) {
  asm volatile("ldmatrix.sync.aligned.m8n8.x4.shared.b16 {%0,%1,%2,%3}, [%4];"
               : "=r"(r[0]), "=r"(r[1]), "=r"(r[2]), "=r"(r[3]) : "r"(a));
}
__device__ __forceinline__ void ldsm4t(uint32_t r[4], uint32_t a) {
  asm volatile("ldmatrix.sync.aligned.m8n8.x4.trans.shared.b16 {%0,%1,%2,%3}, [%4];"
               : "=r"(r[0]), "=r"(r[1]), "=r"(r[2]), "=r"(r[3]) : "r"(a));
}

__device__ __forceinline__ void mma16816(float c[4], const uint32_t a[4],
                                         uint32_t b0, uint32_t b1) {
  asm volatile(
      "mma.sync.aligned.m16n8k16.row.col.f32.bf16.bf16.f32 "
      "{%0,%1,%2,%3},{%4,%5,%6,%7},{%8,%9},{%0,%1,%2,%3};\n"
      : "+f"(c[0]), "+f"(c[1]), "+f"(c[2]), "+f"(c[3])
      : "r"(a[0]), "r"(a[1]), "r"(a[2]), "r"(a[3]), "r"(b0), "r"(b1));
}

// 6-MMA split group with interleaved accumulator targets (breaks RAW chains).
__device__ __forceinline__ void mma_group6(float c0[4], float c1[4],
                                           const uint32_t ah[4], const uint32_t al[4],
                                           const uint32_t bh[4], const uint32_t bl[4]) {
  mma16816(c0, ah, bh[0], bh[1]);
  mma16816(c1, ah, bh[2], bh[3]);
  mma16816(c0, ah, bl[0], bl[1]);
  mma16816(c1, ah, bl[2], bl[3]);
  mma16816(c0, al, bh[0], bh[1]);
  mma16816(c1, al, bh[2], bh[3]);
}

__device__ __forceinline__ void split_pack(float x, float y, uint32_t& h, uint32_t& l) {
  __nv_bfloat162 H = __floats2bfloat162_rn(x, y);
  float hx = __bfloat162float(H.x), hy = __bfloat162float(H.y);
  __nv_bfloat162 Lo = __floats2bfloat162_rn(x - hx, y - hy);
  h = *reinterpret_cast<uint32_t*>(&H);
  l = *reinterpret_cast<uint32_t*>(&Lo);
}

__device__ __forceinline__ float ex2f_(float x) {
  float y;
  asm("ex2.approx.ftz.f32 %0, %1;" : "=f"(y) : "f"(x));
  return y;
}

__device__ __forceinline__ void cp16(uint32_t dst, const void* src) {
  asm volatile("cp.async.cg.shared.global [%0], [%1], 16;" :: "r"(dst), "l"(src));
}

// ---------------------------------------------------------------------------
// Kernel 0a: ONE fused fp32 -> split-bf16 conversion over all 7 tensors.
// Segments: [0,3*NX) = keys/queries/values; [3*NX, +4*NW) = Wk,Wq,Wv,Wu.
// ---------------------------------------------------------------------------
#define NX4 ((B_ * L_ * D_) / 4)   // 2097152
#define NW4 ((D_ * D_) / 4)        // 262144
#define NCONV (3 * NX4 + 4 * NW4)  // 7340032

__global__ void __launch_bounds__(256) convert_all(
    const float* __restrict__ k, const float* __restrict__ q,
    const float* __restrict__ v, const float* __restrict__ wk,
    const float* __restrict__ wq, const float* __restrict__ wv,
    const float* __restrict__ wu) {
  int i = blockIdx.x * 256 + threadIdx.x;
  if (i >= NCONV) return;
  const float* src;
  __nv_bfloat16 *dh, *dl;
  int local;
  if (i < 3 * NX4) {
    int which = i / NX4;
    local = i - which * NX4;
    src = (which == 0) ? k : (which == 1) ? q : v;
    dh = g_Xh + (size_t)which * (B_ * L_ * D_);
    dl = g_Xl + (size_t)which * (B_ * L_ * D_);
  } else {
    int j = i - 3 * NX4;
    int which = j / NW4;
    local = j - which * NW4;
    src = (which == 0) ? wk : (which == 1) ? wq : (which == 2) ? wv : wu;
    dh = g_Wh + (size_t)which * (D_ * D_);
    dl = g_Wl + (size_t)which * (D_ * D_);
  }
  float4 vv = reinterpret_cast<const float4*>(src)[local];
  uint32_t h0, l0, h1, l1;
  split_pack(vv.x, vv.y, h0, l0);
  split_pack(vv.z, vv.w, h1, l1);
  reinterpret_cast<uint32_t*>(dh)[local * 2]     = h0;
  reinterpret_cast<uint32_t*>(dh)[local * 2 + 1] = h1;
  reinterpret_cast<uint32_t*>(dl)[local * 2]     = l0;
  reinterpret_cast<uint32_t*>(dl)[local * 2 + 1] = l1;
}

// Kernel 0b: Zs = split(Z1 + Z2).
__global__ void __launch_bounds__(256) convert_zsum(int n4) {
  int i = blockIdx.x * 256 + threadIdx.x;
  if (i >= n4) return;
  float4 a = reinterpret_cast<const float4*>(g_Z1)[i];
  float4 b = reinterpret_cast<const float4*>(g_Z2)[i];
  float4 s = make_float4(a.x + b.x, a.y + b.y, a.z + b.z, a.w + b.w);
  uint32_t h0, l0, h1, l1;
  split_pack(s.x, s.y, h0, l0);
  split_pack(s.z, s.w, h1, l1);
  reinterpret_cast<uint32_t*>(g_Zh)[i * 2]     = h0;
  reinterpret_cast<uint32_t*>(g_Zh)[i * 2 + 1] = h1;
  reinterpret_cast<uint32_t*>(g_Zl)[i * 2]     = l0;
  reinterpret_cast<uint32_t*>(g_Zl)[i * 2 + 1] = l1;
}

// ---------------------------------------------------------------------------
// GEMM tile machinery: 128x128 CTA tile, BK=64, pitch 72 bf16 (144 B),
// 4 arrays per stage (Ah, Al, Bh, Bl), 3-stage cp.async ring, 1 bar/step.
// ---------------------------------------------------------------------------
#define GARR_B   18432                 // 128 rows * 144 B
#define GSTAGE_B (4 * GARR_B)          // 73728
#define GEMM_SMEM (3 * GSTAGE_B)       // 221184

struct GemmPtrs {
  const __nv_bfloat16 *Ah, *Al, *Bh, *Bl;
};

__device__ __forceinline__ void gemm_issue(
    const GemmPtrs& gp, uint32_t sb, int kc, int tid, int m0, int n0) {
  uint32_t stage = sb + (uint32_t)(kc % 3) * GSTAGE_B;
  int k0 = kc * 64;
  const __nv_bfloat16* ps[4] = {gp.Ah, gp.Al, gp.Bh, gp.Bl};
#pragma unroll
  for (int it = 0; it < 16; it++) {
    int f = tid + it * 256;
    int arr = f >> 10, q = f & 1023;
    int r = q >> 3, c8 = (q & 7) * 8;
    int row = (arr < 2 ? m0 : n0) + r;
    cp16(stage + (uint32_t)(arr * GARR_B + r * 144 + c8 * 2),
         ps[arr] + (size_t)row * D_ + k0 + c8);
  }
  asm volatile("cp.async.commit_group;" ::: "memory");
}

__device__ __forceinline__ void gemm_compute(
    float acc[2][8][4], uint32_t sb, int kc, int lane, int wm, int wn) {
  uint32_t stage = sb + (uint32_t)(kc % 3) * GSTAGE_B;
  uint32_t Ah_s = stage, Al_s = stage + GARR_B;
  uint32_t Bh_s = stage + 2 * GARR_B, Bl_s = stage + 3 * GARR_B;
#pragma unroll
  for (int g = 0; g < 4; g++) {
    uint32_t ah[2][4], al[2][4];
#pragma unroll
    for (int mi = 0; mi < 2; mi++) {
      uint32_t off = (uint32_t)((wm * 32 + mi * 16 + (lane & 15)) * 144 +
                                (g * 16 + ((lane >> 4) << 3)) * 2);
      ldsm4(ah[mi], Ah_s + off);
      ldsm4(al[mi], Al_s + off);
    }
#pragma unroll
    for (int np = 0; np < 4; np++) {
      uint32_t bhv[4], blv[4];
      uint32_t off = (uint32_t)((wn * 64 + np * 16 + ((lane >> 4) << 3) + (lane & 7)) * 144 +
                                (g * 16 + (((lane >> 3) & 1) << 3)) * 2);
      ldsm4(bhv, Bh_s + off);
      ldsm4(blv, Bl_s + off);
#pragma unroll
      for (int mi = 0; mi < 2; mi++)
        mma_group6(acc[mi][np * 2], acc[mi][np * 2 + 1], ah[mi], al[mi], bhv, blv);
    }
  }
}

__device__ __forceinline__ void gemm_mainloop(
    float acc[2][8][4], const GemmPtrs& gp, uint32_t sb, int tid, int lane,
    int wm, int wn, int m0, int n0) {
  gemm_issue(gp, sb, 0, tid, m0, n0);
  gemm_issue(gp, sb, 1, tid, m0, n0);
  for (int t = 0; t < 16; t++) {
    if (t < 15) asm volatile("cp.async.wait_group 1;" ::: "memory");
    else        asm volatile("cp.async.wait_group 0;" ::: "memory");
    __syncthreads();
    if (t + 2 < 16) gemm_issue(gp, sb, t + 2, tid, m0, n0);
    gemm_compute(acc, sb, t, lane, wm, wn);
  }
}

// ---------------------------------------------------------------------------
// Kernel 1: projections. Y[c][t] = W[c][:].X[t][:]; split-bf16 output * scl.
// ---------------------------------------------------------------------------
__global__ void __launch_bounds__(256) proj_mma2() {
  extern __shared__ char smg[];
  uint32_t sb = sptr(smg);
  const float QS = 0.08838834764831845f * 1.4426950408889634f;

  int z = blockIdx.z, pj = z >> 2, b = z & 3;
  GemmPtrs gp;
  gp.Ah = g_Wh + (size_t)pj * (D_ * D_);
  gp.Al = g_Wl + (size_t)pj * (D_ * D_);
  gp.Bh = g_Xh + ((size_t)pj * B_ + b) * (L_ * D_);
  gp.Bl = g_Xl + ((size_t)pj * B_ + b) * (L_ * D_);
  __nv_bfloat16* Yh = ((pj == 0) ? g_Ykh : (pj == 1) ? g_Yqh : g_Yvh) + (size_t)b * D_ * L_;
  __nv_bfloat16* Yl = ((pj == 0) ? g_Ykl : (pj == 1) ? g_Yql : g_Yvl) + (size_t)b * D_ * L_;
  float scl = (pj == 0) ? 1.0f : QS;

  int m0 = blockIdx.y * 128, n0 = blockIdx.x * 128;
  int tid = threadIdx.x, lane = tid & 31, w = tid >> 5;
  int wm = w & 3, wn = w >> 2;

  float acc[2][8][4];
#pragma unroll
  for (int mi = 0; mi < 2; mi++)
#pragma unroll
    for (int t8 = 0; t8 < 8; t8++)
#pragma unroll
      for (int q = 0; q < 4; q++) acc[mi][t8][q] = 0.0f;

  gemm_mainloop(acc, gp, sb, tid, lane, wm, wn, m0, n0);

#pragma unroll
  for (int mi = 0; mi < 2; mi++)
#pragma unroll
    for (int t8 = 0; t8 < 8; t8++) {
      int row = m0 + wm * 32 + mi * 16 + (lane >> 2);
      int col = n0 + wn * 64 + t8 * 8 + (lane & 3) * 2;
      uint32_t h, l;
      split_pack(acc[mi][t8][0] * scl, acc[mi][t8][1] * scl, h, l);
      *(uint32_t*)&Yh[(size_t)row * L_ + col] = h;
      *(uint32_t*)&Yl[(size_t)row * L_ + col] = l;
      split_pack(acc[mi][t8][2] * scl, acc[mi][t8][3] * scl, h, l);
      *(uint32_t*)&Yh[(size_t)(row + 8) * L_ + col] = h;
      *(uint32_t*)&Yl[(size_t)(row + 8) * L_ + col] = l;
    }
}

// ---------------------------------------------------------------------------
// Kernel 3: output projection. out[t][n] = Zs[t][:].Wu[n][:] + bu[n].
// ---------------------------------------------------------------------------
__global__ void __launch_bounds__(256) final_mma2(const float* __restrict__ bu,
                                                  float* __restrict__ out) {
  extern __shared__ char smg[];
  uint32_t sb = sptr(smg);

  int b = blockIdx.z;
  GemmPtrs gp;
  gp.Ah = g_Zh + (size_t)b * (L_ * D_);
  gp.Al = g_Zl + (size_t)b * (L_ * D_);
  gp.Bh = g_Wh + (size_t)3 * (D_ * D_);
  gp.Bl = g_Wl + (size_t)3 * (D_ * D_);

  int m0 = blockIdx.y * 128, n0 = blockIdx.x * 128;
  int tid = threadIdx.x, lane = tid & 31, w = tid >> 5;
  int wm = w & 3, wn = w >> 2;

  float acc[2][8][4];
#pragma unroll
  for (int mi = 0; mi < 2; mi++)
#pragma unroll
    for (int t8 = 0; t8 < 8; t8++)
#pragma unroll
      for (int q = 0; q < 4; q++) acc[mi][t8][q] = 0.0f;

  gemm_mainloop(acc, gp, sb, tid, lane, wm, wn, m0, n0);

  float* Cb = out + (size_t)b * L_ * D_;
#pragma unroll
  for (int mi = 0; mi < 2; mi++)
#pragma unroll
    for (int t8 = 0; t8 < 8; t8++) {
      int row = m0 + wm * 32 + mi * 16 + (lane >> 2);
      int col = n0 + wn * 64 + t8 * 8 + (lane & 3) * 2;
      float2 bias = *(const float2*)&bu[col];
      float2 v0 = make_float2(acc[mi][t8][0] + bias.x, acc[mi][t8][1] + bias.y);
      float2 v1 = make_float2(acc[mi][t8][2] + bias.x, acc[mi][t8][3] + bias.y);
      *(float2*)&Cb[(size_t)row * D_ + col] = v0;
      *(float2*)&Cb[(size_t)(row + 8) * D_ + col] = v1;
    }
}

// ---------------------------------------------------------------------------
// Kernel 2: fused dual flash attention. 512 threads / 16 warps:
// 8 m-groups x 2 key-splits (no-max softmax makes the key dim additive, so
// key-split warps run fully decoupled; one smem reduction at the end).
// 3-stage K ring, one __syncthreads per tile. Split-3 bf16 MMA core.
// ---------------------------------------------------------------------------
#define AP_      136
#define QH_OFF   0
#define QL_OFF   (128 * AP_ * 2)
#define K_OFF    (2 * 128 * AP_ * 2)       // 69632
#define KHALF    (64 * AP_ * 2)            // 17408
#define KSTAGE   (2 * KHALF)               // 34816
#define ATTN_SMEM (K_OFF + 3 * KSTAGE)     // 174080

__global__ void __launch_bounds__(512, 1) attn_mma() {
  extern __shared__ char smc[];
  uint32_t sb = sptr(smc);

  int bh = blockIdx.y, b = bh >> 3, head = bh & 7;
  int xb = blockIdx.x;
  bool isQ = (xb < 16);
  int r0 = (isQ ? xb : xb - 16) * 128;

  size_t hb = (size_t)(b * D_ + head * DK_) * L_;
  const __nv_bfloat16* Qh_g = (isQ ? g_Yqh : g_Yvh) + hb + (size_t)r0 * DK_;
  const __nv_bfloat16* Ql_g = (isQ ? g_Yql : g_Yvl) + hb + (size_t)r0 * DK_;
  const __nv_bfloat16* Kh_g = g_Ykh + hb;
  const __nv_bfloat16* Kl_g = g_Ykl + hb;

  int tid = threadIdx.x, lane = tid & 31, w = tid >> 5;
  int wm = w >> 1, wj = w & 1;   // m-group 0..7 (16 rows), key-split 0..1

  // Prologue: Q (hi+lo, 128x128) + K tiles 0,1.
#pragma unroll
  for (int it = 0; it < 8; it++) {
    int f = tid + it * 512;                // 0..4095
    int half = f >> 11, r = (f >> 4) & 127, c = (f & 15) * 8;
    cp16(sb + (half ? QL_OFF : QH_OFF) + r * (AP_ * 2) + c * 2,
         (half ? Ql_g : Qh_g) + (size_t)r * DK_ + c);
  }
#pragma unroll
  for (int it = 0; it < 4; it++) {
    int f = tid + it * 512;                // 0..2047
    int half = f >> 10, r = (f >> 4) & 63, c = (f & 15) * 8;
    cp16(sb + K_OFF + half * KHALF + r * (AP_ * 2) + c * 2,
         (half ? Kl_g : Kh_g) + (size_t)r * DK_ + c);
  }
  asm volatile("cp.async.commit_group;" ::: "memory");
#pragma unroll
  for (int it = 0; it < 4; it++) {
    int f = tid + it * 512;
    int half = f >> 10, r = (f >> 4) & 63, c = (f & 15) * 8;
    cp16(sb + K_OFF + KSTAGE + half * KHALF + r * (AP_ * 2) + c * 2,
         (half ? Kl_g : Kh_g) + (size_t)(64 + r) * DK_ + c);
  }
  asm volatile("cp.async.commit_group;" ::: "memory");

  float acc[16][4];
#pragma unroll
  for (int d = 0; d < 16; d++)
#pragma unroll
    for (int q = 0; q < 4; q++) acc[d][q] = 0.0f;
  float l_a = 0.0f, l_b = 0.0f;

  for (int t = 0; t < 32; t++) {
    if (t < 31) asm volatile("cp.async.wait_group 1;" ::: "memory");
    else        asm volatile("cp.async.wait_group 0;" ::: "memory");
    __syncthreads();
    if (t + 2 < 32) {
      int buf = (t + 2) % 3;
#pragma unroll
      for (int it = 0; it < 4; it++) {
        int f = tid + it * 512;
        int half = f >> 10, r = (f >> 4) & 63, c = (f & 15) * 8;
        cp16(sb + K_OFF + buf * KSTAGE + half * KHALF + r * (AP_ * 2) + c * 2,
             (half ? Kl_g : Kh_g) + (size_t)((t + 2) * 64 + r) * DK_ + c);
      }
      asm volatile("cp.async.commit_group;" ::: "memory");
    }
    uint32_t KH = sb + K_OFF + (uint32_t)(t % 3) * KSTAGE;
    uint32_t KL = KH + KHALF;

    // Phase A: S[16 x 32] per warp (this warp's 32 keys), split 3-term.
    float S[4][4];
#pragma unroll
    for (int i = 0; i < 4; i++)
#pragma unroll
      for (int q = 0; q < 4; q++) S[i][q] = 0.0f;

#pragma unroll
    for (int g = 0; g < 8; g++) {
      uint32_t ah[4], al[4];
      uint32_t qoff = (uint32_t)((wm * 16 + (lane & 15)) * (AP_ * 2) +
                                 (g * 16 + ((lane >> 4) << 3)) * 2);
      ldsm4(ah, sb + QH_OFF + qoff);
      ldsm4(al, sb + QL_OFF + qoff);
#pragma unroll
      for (int np = 0; np < 2; np++) {
        uint32_t bhv[4], blv[4];
        uint32_t koff = (uint32_t)((wj * 32 + np * 16 + ((lane >> 4) << 3) + (lane & 7)) * (AP_ * 2) +
                                   (g * 16 + (((lane >> 3) & 1) << 3)) * 2);
        ldsm4(bhv, KH + koff);
        ldsm4(blv, KL + koff);
        mma_group6(S[np * 2], S[np * 2 + 1], ah, al, bhv, blv);
      }
    }

    // p = 2^S directly (bounded logits, no max subtraction needed).
    float sa = 0.0f, sb2 = 0.0f;
#pragma unroll
    for (int i = 0; i < 4; i++) {
      S[i][0] = ex2f_(S[i][0]);
      S[i][1] = ex2f_(S[i][1]);
      sa += S[i][0] + S[i][1];
      S[i][2] = ex2f_(S[i][2]);
      S[i][3] = ex2f_(S[i][3]);
      sb2 += S[i][2] + S[i][3];
    }
    sa += __shfl_xor_sync(0xffffffffu, sa, 1);
    sa += __shfl_xor_sync(0xffffffffu, sa, 2);
    sb2 += __shfl_xor_sync(0xffffffffu, sb2, 1);
    sb2 += __shfl_xor_sync(0xffffffffu, sb2, 2);
    l_a += sa;
    l_b += sb2;

    // Phase C: acc += P[16x32] @ K[32x128] (split P in regs, trans ldmatrix K).
#pragma unroll
    for (int g2 = 0; g2 < 2; g2++) {
      uint32_t pah[4], pal[4];
      split_pack(S[2 * g2][0],     S[2 * g2][1],     pah[0], pal[0]);
      split_pack(S[2 * g2][2],     S[2 * g2][3],     pah[1], pal[1]);
      split_pack(S[2 * g2 + 1][0], S[2 * g2 + 1][1], pah[2], pal[2]);
      split_pack(S[2 * g2 + 1][2], S[2 * g2 + 1][3], pah[3], pal[3]);
#pragma unroll
      for (int dp = 0; dp < 8; dp++) {
        uint32_t bhv[4], blv[4];
        uint32_t koff = (uint32_t)((wj * 32 + g2 * 16 + (lane & 15)) * (AP_ * 2) +
                                   (dp * 16 + ((lane >> 4) << 3)) * 2);
        ldsm4t(bhv, KH + koff);
        ldsm4t(blv, KL + koff);
        mma_group6(acc[dp * 2], acc[dp * 2 + 1], pah, pal, bhv, blv);
      }
    }
  }

  // Cross-warp reduction over the 2 key-splits (Q smem area is free now).
  __syncthreads();
  float* red = (float*)smc;                 // [128 rows][128 d] fp32 = 64 KB
  float* lred = red + 128 * 128;            // [128 rows] fp32
  int row_a = wm * 16 + (lane >> 2);
  int row_b = row_a + 8;
  if (wj == 1) {
#pragma unroll
    for (int d = 0; d < 16; d++) {
      int col = d * 8 + (lane & 3) * 2;
      *(float2*)&red[row_a * 128 + col] = make_float2(acc[d][0], acc[d][1]);
      *(float2*)&red[row_b * 128 + col] = make_float2(acc[d][2], acc[d][3]);
    }
    if ((lane & 3) == 0) { lred[row_a] = l_a; lred[row_b] = l_b; }
  }
  __syncthreads();
  if (wj == 0) {
    float la = l_a + lred[row_a];
    float lb = l_b + lred[row_b];
    float inva = 0.5f / la, invb = 0.5f / lb;
    float* Z = (isQ ? g_Z1 : g_Z2) + (size_t)b * L_ * D_;
#pragma unroll
    for (int d = 0; d < 16; d++) {
      int col = d * 8 + (lane & 3) * 2;
      float2 pa = *(const float2*)&red[row_a * 128 + col];
      float2 pb = *(const float2*)&red[row_b * 128 + col];
      float2 v0 = make_float2((acc[d][0] + pa.x) * inva, (acc[d][1] + pa.y) * inva);
      float2 v1 = make_float2((acc[d][2] + pb.x) * invb, (acc[d][3] + pb.y) * invb);
      int gcol = head * DK_ + col;
      *(float2*)&Z[(size_t)(r0 + row_a) * D_ + gcol] = v0;
      *(float2*)&Z[(size_t)(r0 + row_b) * D_ + gcol] = v1;
    }
  }
}

// ---------------------------------------------------------------------------
extern "C" void kernel_launch(void* const* d_in, const int* in_sizes, int n_in,
                              void* d_out, int out_size) {
  (void)in_sizes; (void)n_in; (void)out_size;
  const float* keys    = (const float*)d_in[0];
  const float* queries = (const float*)d_in[1];
  const float* values  = (const float*)d_in[2];
  const float* Wk      = (const float*)d_in[3];
  const float* Wq      = (const float*)d_in[4];
  const float* Wv      = (const float*)d_in[5];
  const float* Wu      = (const float*)d_in[6];
  const float* bu      = (const float*)d_in[7];
  float* out = (float*)d_out;

  cudaFuncSetAttribute(attn_mma, cudaFuncAttributeMaxDynamicSharedMemorySize,
                       ATTN_SMEM);
  cudaFuncSetAttribute(proj_mma2, cudaFuncAttributeMaxDynamicSharedMemorySize,
                       GEMM_SMEM);
  cudaFuncSetAttribute(final_mma2, cudaFuncAttributeMaxDynamicSharedMemorySize,
                       GEMM_SMEM);

  convert_all<<<(NCONV + 255) / 256, 256>>>(keys, queries, values, Wk, Wq, Wv, Wu);
  proj_mma2<<<dim3(16, 8, 12), 256, GEMM_SMEM>>>();
  attn_mma<<<dim3(32, 32), 512, ATTN_SMEM>>>();
  convert_zsum<<<NX4 / 256, 256>>>(NX4);
  final_mma2<<<dim3(8, 16, 4), 256, GEMM_SMEM>>>(bu, out);
}

// round 12
// speedup vs baseline: 1.0470x; 1.0470x over previous
#include <cuda_runtime.h>
#include <cuda_bf16.h>
#include <stdint.h>

// Shapes fixed by the problem: b=4, l=2048, d_model=1024, h=8, dk=128.
#define B_  4
#define L_  2048
#define D_  1024
#define H_  8
#define DK_ 128

// Pre-split inputs/weights (hi + residual lo bf16).
__device__ __nv_bfloat16 g_Xh[3 * B_ * L_ * D_];   // k/q/v inputs, [pj][b][t][d]
__device__ __nv_bfloat16 g_Xl[3 * B_ * L_ * D_];
__device__ __nv_bfloat16 g_Wh[4 * D_ * D_];        // Wk,Wq,Wv,Wu, [pj][c][d]
__device__ __nv_bfloat16 g_Wl[4 * D_ * D_];

// Projections, split bf16, channel-major Y[b][c][t]. Yq/Yv carry dk^-.5*log2e.
__device__ __nv_bfloat16 g_Ykh[B_ * D_ * L_];
__device__ __nv_bfloat16 g_Ykl[B_ * D_ * L_];
__device__ __nv_bfloat16 g_Yqh[B_ * D_ * L_];
__device__ __nv_bfloat16 g_Yql[B_ * D_ * L_];
__device__ __nv_bfloat16 g_Yvh[B_ * D_ * L_];
__device__ __nv_bfloat16 g_Yvl[B_ * D_ * L_];

// Attention outputs (fp32) and their summed split-bf16 form.
__device__ float g_Z1[B_ * L_ * D_];
__device__ float g_Z2[B_ * L_ * D_];
__device__ __nv_bfloat16 g_Zh[B_ * L_ * D_];
__device__ __nv_bfloat16 g_Zl[B_ * L_ * D_];

// ---------------------------------------------------------------------------
// Helpers
// ---------------------------------------------------------------------------
__device__ __forceinline__ uint32_t sptr(const void* p) {
  return (uint32_t)__cvta_generic_to_shared(p);
}

__device__ __forceinline__ void ldsm4(uint32_t r[4], uint32_t a) {
  asm volatile("ldmatrix.sync.aligned.m8n8.x4.shared.b16 {%0,%1,%2,%3}, [%4];"
               : "=r"(r[0]), "=r"(r[1]), "=r"(r[2]), "=r"(r[3]) : "r"(a));
}
__device__ __forceinline__ void ldsm4t(uint32_t r[4], uint32_t a) {
  asm volatile("ldmatrix.sync.aligned.m8n8.x4.trans.shared.b16 {%0,%1,%2,%3}, [%4];"
               : "=r"(r[0]), "=r"(r[1]), "=r"(r[2]), "=r"(r[3]) : "r"(a));
}

__device__ __forceinline__ void mma16816(float c[4], const uint32_t a[4],
                                         uint32_t b0, uint32_t b1) {
  asm volatile(
      "mma.sync.aligned.m16n8k16.row.col.f32.bf16.bf16.f32 "
      "{%0,%1,%2,%3},{%4,%5,%6,%7},{%8,%9},{%0,%1,%2,%3};\n"
      : "+f"(c[0]), "+f"(c[1]), "+f"(c[2]), "+f"(c[3])
      : "r"(a[0]), "r"(a[1]), "r"(a[2]), "r"(a[3]), "r"(b0), "r"(b1));
}

// 6-MMA split group with interleaved accumulator targets (breaks RAW chains).
__device__ __forceinline__ void mma_group6(float c0[4], float c1[4],
                                           const uint32_t ah[4], const uint32_t al[4],
                                           const uint32_t bh[4], const uint32_t bl[4]) {
  mma16816(c0, ah, bh[0], bh[1]);
  mma16816(c1, ah, bh[2], bh[3]);
  mma16816(c0, ah, bl[0], bl[1]);
  mma16816(c1, ah, bl[2], bl[3]);
  mma16816(c0, al, bh[0], bh[1]);
  mma16816(c1, al, bh[2], bh[3]);
}

// Round-to-nearest split (epilogues / converts).
__device__ __forceinline__ void split_pack(float x, float y, uint32_t& h, uint32_t& l) {
  __nv_bfloat162 H = __floats2bfloat162_rn(x, y);
  float hx = __bfloat162float(H.x), hy = __bfloat162float(H.y);
  __nv_bfloat162 Lo = __floats2bfloat162_rn(x - hx, y - hy);
  h = *reinterpret_cast<uint32_t*>(&H);
  l = *reinterpret_cast<uint32_t*>(&Lo);
}

// Cheap truncation split for NON-NEGATIVE values (softmax p): 6 ops.
__device__ __forceinline__ void trunc_split(float x, float y, uint32_t& h, uint32_t& l) {
  uint32_t xb = __float_as_uint(x), yb = __float_as_uint(y);
  h = __byte_perm(xb, yb, 0x7632);
  float xl = x - __uint_as_float(xb & 0xFFFF0000u);
  float yl = y - __uint_as_float(yb & 0xFFFF0000u);
  l = __byte_perm(__float_as_uint(xl), __float_as_uint(yl), 0x7632);
}

__device__ __forceinline__ float ex2f_(float x) {
  float y;
  asm("ex2.approx.ftz.f32 %0, %1;" : "=f"(y) : "f"(x));
  return y;
}

__device__ __forceinline__ void cp16(uint32_t dst, const void* src) {
  asm volatile("cp.async.cg.shared.global [%0], [%1], 16;" :: "r"(dst), "l"(src));
}

// ---------------------------------------------------------------------------
// Kernel 0a: ONE fused fp32 -> split-bf16 conversion over all 7 tensors.
// ---------------------------------------------------------------------------
#define NX4 ((B_ * L_ * D_) / 4)
#define NW4 ((D_ * D_) / 4)
#define NCONV (3 * NX4 + 4 * NW4)

__global__ void __launch_bounds__(256) convert_all(
    const float* __restrict__ k, const float* __restrict__ q,
    const float* __restrict__ v, const float* __restrict__ wk,
    const float* __restrict__ wq, const float* __restrict__ wv,
    const float* __restrict__ wu) {
  int i = blockIdx.x * 256 + threadIdx.x;
  if (i >= NCONV) return;
  const float* src;
  __nv_bfloat16 *dh, *dl;
  int local;
  if (i < 3 * NX4) {
    int which = i / NX4;
    local = i - which * NX4;
    src = (which == 0) ? k : (which == 1) ? q : v;
    dh = g_Xh + (size_t)which * (B_ * L_ * D_);
    dl = g_Xl + (size_t)which * (B_ * L_ * D_);
  } else {
    int j = i - 3 * NX4;
    int which = j / NW4;
    local = j - which * NW4;
    src = (which == 0) ? wk : (which == 1) ? wq : (which == 2) ? wv : wu;
    dh = g_Wh + (size_t)which * (D_ * D_);
    dl = g_Wl + (size_t)which * (D_ * D_);
  }
  float4 vv = reinterpret_cast<const float4*>(src)[local];
  uint32_t h0, l0, h1, l1;
  split_pack(vv.x, vv.y, h0, l0);
  split_pack(vv.z, vv.w, h1, l1);
  reinterpret_cast<uint32_t*>(dh)[local * 2]     = h0;
  reinterpret_cast<uint32_t*>(dh)[local * 2 + 1] = h1;
  reinterpret_cast<uint32_t*>(dl)[local * 2]     = l0;
  reinterpret_cast<uint32_t*>(dl)[local * 2 + 1] = l1;
}

// Kernel 0b: Zs = split(Z1 + Z2).
__global__ void __launch_bounds__(256) convert_zsum(int n4) {
  int i = blockIdx.x * 256 + threadIdx.x;
  if (i >= n4) return;
  float4 a = reinterpret_cast<const float4*>(g_Z1)[i];
  float4 b = reinterpret_cast<const float4*>(g_Z2)[i];
  float4 s = make_float4(a.x + b.x, a.y + b.y, a.z + b.z, a.w + b.w);
  uint32_t h0, l0, h1, l1;
  split_pack(s.x, s.y, h0, l0);
  split_pack(s.z, s.w, h1, l1);
  reinterpret_cast<uint32_t*>(g_Zh)[i * 2]     = h0;
  reinterpret_cast<uint32_t*>(g_Zh)[i * 2 + 1] = h1;
  reinterpret_cast<uint32_t*>(g_Zl)[i * 2]     = l0;
  reinterpret_cast<uint32_t*>(g_Zl)[i * 2 + 1] = l1;
}

// ---------------------------------------------------------------------------
// GEMM: 128x128 CTA tile, BK=32, pitch 40 bf16 (80 B), 2-stage cp.async ring,
// one __syncthreads per k-step. 80 KB smem -> 2 CTAs/SM (regs capped at 128).
// ---------------------------------------------------------------------------
#define GARR_B   10240                 // 128 rows * 80 B
#define GSTAGE_B (4 * GARR_B)          // 40960
#define GEMM_SMEM (2 * GSTAGE_B)       // 81920

struct GemmPtrs {
  const __nv_bfloat16 *Ah, *Al, *Bh, *Bl;
};

__device__ __forceinline__ void gemm_issue(
    const GemmPtrs& gp, uint32_t sb, int kc, int tid, int m0, int n0) {
  uint32_t stage = sb + (uint32_t)(kc & 1) * GSTAGE_B;
  int k0 = kc * 32;
  const __nv_bfloat16* ps[4] = {gp.Ah, gp.Al, gp.Bh, gp.Bl};
#pragma unroll
  for (int it = 0; it < 8; it++) {
    int f = tid + it * 256;            // 0..2047
    int arr = f >> 9, q = f & 511;     // 512 cp16 per array
    int r = q >> 2, c8 = (q & 3) * 8;  // row, bf16 col
    int row = (arr < 2 ? m0 : n0) + r;
    cp16(stage + (uint32_t)(arr * GARR_B + r * 80 + c8 * 2),
         ps[arr] + (size_t)row * D_ + k0 + c8);
  }
  asm volatile("cp.async.commit_group;" ::: "memory");
}

__device__ __forceinline__ void gemm_compute(
    float acc[2][8][4], uint32_t sb, int kc, int lane, int wm, int wn) {
  uint32_t stage = sb + (uint32_t)(kc & 1) * GSTAGE_B;
  uint32_t Ah_s = stage, Al_s = stage + GARR_B;
  uint32_t Bh_s = stage + 2 * GARR_B, Bl_s = stage + 3 * GARR_B;
#pragma unroll
  for (int g = 0; g < 2; g++) {
    uint32_t ah[2][4], al[2][4];
#pragma unroll
    for (int mi = 0; mi < 2; mi++) {
      uint32_t off = (uint32_t)((wm * 32 + mi * 16 + (lane & 15)) * 80 +
                                (g * 16 + ((lane >> 4) << 3)) * 2);
      ldsm4(ah[mi], Ah_s + off);
      ldsm4(al[mi], Al_s + off);
    }
#pragma unroll
    for (int np = 0; np < 4; np++) {
      uint32_t bhv[4], blv[4];
      uint32_t off = (uint32_t)((wn * 64 + np * 16 + ((lane >> 4) << 3) + (lane & 7)) * 80 +
                                (g * 16 + (((lane >> 3) & 1) << 3)) * 2);
      ldsm4(bhv, Bh_s + off);
      ldsm4(blv, Bl_s + off);
#pragma unroll
      for (int mi = 0; mi < 2; mi++)
        mma_group6(acc[mi][np * 2], acc[mi][np * 2 + 1], ah[mi], al[mi], bhv, blv);
    }
  }
}

// 2-stage mainloop, 32 k-steps: wait(t), bar, issue(t+1), compute(t).
// issue(t+1) reuses buffer(t-1), whose compute finished before this bar.
__device__ __forceinline__ void gemm_mainloop(
    float acc[2][8][4], const GemmPtrs& gp, uint32_t sb, int tid, int lane,
    int wm, int wn, int m0, int n0) {
  gemm_issue(gp, sb, 0, tid, m0, n0);
  for (int t = 0; t < 32; t++) {
    asm volatile("cp.async.wait_group 0;" ::: "memory");
    __syncthreads();
    if (t + 1 < 32) gemm_issue(gp, sb, t + 1, tid, m0, n0);
    gemm_compute(acc, sb, t, lane, wm, wn);
  }
}

// ---------------------------------------------------------------------------
// Kernel 1: projections. Y[c][t] = W[c][:].X[t][:]; split-bf16 output * scl.
// ---------------------------------------------------------------------------
__global__ void __launch_bounds__(256, 2) proj_mma2() {
  extern __shared__ char smg[];
  uint32_t sb = sptr(smg);
  const float QS = 0.08838834764831845f * 1.4426950408889634f;

  int z = blockIdx.z, pj = z >> 2, b = z & 3;
  GemmPtrs gp;
  gp.Ah = g_Wh + (size_t)pj * (D_ * D_);
  gp.Al = g_Wl + (size_t)pj * (D_ * D_);
  gp.Bh = g_Xh + ((size_t)pj * B_ + b) * (L_ * D_);
  gp.Bl = g_Xl + ((size_t)pj * B_ + b) * (L_ * D_);
  __nv_bfloat16* Yh = ((pj == 0) ? g_Ykh : (pj == 1) ? g_Yqh : g_Yvh) + (size_t)b * D_ * L_;
  __nv_bfloat16* Yl = ((pj == 0) ? g_Ykl : (pj == 1) ? g_Yql : g_Yvl) + (size_t)b * D_ * L_;
  float scl = (pj == 0) ? 1.0f : QS;

  int m0 = blockIdx.y * 128, n0 = blockIdx.x * 128;
  int tid = threadIdx.x, lane = tid & 31, w = tid >> 5;
  int wm = w & 3, wn = w >> 2;

  float acc[2][8][4];
#pragma unroll
  for (int mi = 0; mi < 2; mi++)
#pragma unroll
    for (int t8 = 0; t8 < 8; t8++)
#pragma unroll
      for (int q = 0; q < 4; q++) acc[mi][t8][q] = 0.0f;

  gemm_mainloop(acc, gp, sb, tid, lane, wm, wn, m0, n0);

#pragma unroll
  for (int mi = 0; mi < 2; mi++)
#pragma unroll
    for (int t8 = 0; t8 < 8; t8++) {
      int row = m0 + wm * 32 + mi * 16 + (lane >> 2);
      int col = n0 + wn * 64 + t8 * 8 + (lane & 3) * 2;
      uint32_t h, l;
      split_pack(acc[mi][t8][0] * scl, acc[mi][t8][1] * scl, h, l);
      *(uint32_t*)&Yh[(size_t)row * L_ + col] = h;
      *(uint32_t*)&Yl[(size_t)row * L_ + col] = l;
      split_pack(acc[mi][t8][2] * scl, acc[mi][t8][3] * scl, h, l);
      *(uint32_t*)&Yh[(size_t)(row + 8) * L_ + col] = h;
      *(uint32_t*)&Yl[(size_t)(row + 8) * L_ + col] = l;
    }
}

// ---------------------------------------------------------------------------
// Kernel 3: output projection. out[t][n] = Zs[t][:].Wu[n][:] + bu[n].
// ---------------------------------------------------------------------------
__global__ void __launch_bounds__(256, 2) final_mma2(const float* __restrict__ bu,
                                                     float* __restrict__ out) {
  extern __shared__ char smg[];
  uint32_t sb = sptr(smg);

  int b = blockIdx.z;
  GemmPtrs gp;
  gp.Ah = g_Zh + (size_t)b * (L_ * D_);
  gp.Al = g_Zl + (size_t)b * (L_ * D_);
  gp.Bh = g_Wh + (size_t)3 * (D_ * D_);
  gp.Bl = g_Wl + (size_t)3 * (D_ * D_);

  int m0 = blockIdx.y * 128, n0 = blockIdx.x * 128;
  int tid = threadIdx.x, lane = tid & 31, w = tid >> 5;
  int wm = w & 3, wn = w >> 2;

  float acc[2][8][4];
#pragma unroll
  for (int mi = 0; mi < 2; mi++)
#pragma unroll
    for (int t8 = 0; t8 < 8; t8++)
#pragma unroll
      for (int q = 0; q < 4; q++) acc[mi][t8][q] = 0.0f;

  gemm_mainloop(acc, gp, sb, tid, lane, wm, wn, m0, n0);

  float* Cb = out + (size_t)b * L_ * D_;
#pragma unroll
  for (int mi = 0; mi < 2; mi++)
#pragma unroll
    for (int t8 = 0; t8 < 8; t8++) {
      int row = m0 + wm * 32 + mi * 16 + (lane >> 2);
      int col = n0 + wn * 64 + t8 * 8 + (lane & 3) * 2;
      float2 bias = *(const float2*)&bu[col];
      float2 v0 = make_float2(acc[mi][t8][0] + bias.x, acc[mi][t8][1] + bias.y);
      float2 v1 = make_float2(acc[mi][t8][2] + bias.x, acc[mi][t8][3] + bias.y);
      *(float2*)&Cb[(size_t)row * D_ + col] = v0;
      *(float2*)&Cb[(size_t)(row + 8) * D_ + col] = v1;
    }
}

// ---------------------------------------------------------------------------
// Kernel 2: fused dual flash attention. 256 threads / 8 warps (m16 each),
// BN=64 keys/tile, 3-stage K ring, one __syncthreads per tile.
// Q fragments hoisted out of the tile loop (invariant). No-max softmax.
// ---------------------------------------------------------------------------
#define AP_      136
#define QH_OFF   0
#define QL_OFF   (128 * AP_ * 2)
#define K_OFF    (2 * 128 * AP_ * 2)       // 69632
#define KHALF    (64 * AP_ * 2)            // 17408
#define KSTAGE   (2 * KHALF)               // 34816
#define ATTN_SMEM (K_OFF + 3 * KSTAGE)     // 174080

__global__ void __launch_bounds__(256, 1) attn_mma() {
  extern __shared__ char smc[];
  uint32_t sb = sptr(smc);

  int bh = blockIdx.y, b = bh >> 3, head = bh & 7;
  int xb = blockIdx.x;
  bool isQ = (xb < 16);
  int r0 = (isQ ? xb : xb - 16) * 128;

  size_t hb = (size_t)(b * D_ + head * DK_) * L_;
  const __nv_bfloat16* Qh_g = (isQ ? g_Yqh : g_Yvh) + hb + (size_t)r0 * DK_;
  const __nv_bfloat16* Ql_g = (isQ ? g_Yql : g_Yvl) + hb + (size_t)r0 * DK_;
  const __nv_bfloat16* Kh_g = g_Ykh + hb;
  const __nv_bfloat16* Kl_g = g_Ykl + hb;

  int tid = threadIdx.x, lane = tid & 31, w = tid >> 5;

  // Prologue: group0 = Q(hi+lo) + K tile 0; group1 = K tile 1.
#pragma unroll
  for (int it = 0; it < 16; it++) {
    int f = tid + it * 256;
    int half = f >> 11, r = (f >> 4) & 127, c = (f & 15) * 8;
    cp16(sb + (half ? QL_OFF : QH_OFF) + r * (AP_ * 2) + c * 2,
         (half ? Ql_g : Qh_g) + (size_t)r * DK_ + c);
  }
#pragma unroll
  for (int it = 0; it < 8; it++) {
    int f = tid + it * 256;
    int half = f >> 10, r = (f >> 4) & 63, c = (f & 15) * 8;
    cp16(sb + K_OFF + half * KHALF + r * (AP_ * 2) + c * 2,
         (half ? Kl_g : Kh_g) + (size_t)r * DK_ + c);
  }
  asm volatile("cp.async.commit_group;" ::: "memory");
#pragma unroll
  for (int it = 0; it < 8; it++) {
    int f = tid + it * 256;
    int half = f >> 10, r = (f >> 4) & 63, c = (f & 15) * 8;
    cp16(sb + K_OFF + KSTAGE + half * KHALF + r * (AP_ * 2) + c * 2,
         (half ? Kl_g : Kh_g) + (size_t)(64 + r) * DK_ + c);
  }
  asm volatile("cp.async.commit_group;" ::: "memory");

  // Q fragments are loop-invariant: load them once.
  asm volatile("cp.async.wait_group 1;" ::: "memory");   // group0 (Q + K0) done
  __syncthreads();
  uint32_t qh[8][4], ql[8][4];
#pragma unroll
  for (int g = 0; g < 8; g++) {
    uint32_t qoff = (uint32_t)((w * 16 + (lane & 15)) * (AP_ * 2) +
                               (g * 16 + ((lane >> 4) << 3)) * 2);
    ldsm4(qh[g], sb + QH_OFF + qoff);
    ldsm4(ql[g], sb + QL_OFF + qoff);
  }

  float acc[16][4];
#pragma unroll
  for (int d = 0; d < 16; d++)
#pragma unroll
    for (int q = 0; q < 4; q++) acc[d][q] = 0.0f;
  float l_a = 0.0f, l_b = 0.0f;

  for (int t = 0; t < 32; t++) {
    if (t < 31) asm volatile("cp.async.wait_group 1;" ::: "memory");
    else        asm volatile("cp.async.wait_group 0;" ::: "memory");
    __syncthreads();
    if (t + 2 < 32) {
      int buf = (t + 2) % 3;
#pragma unroll
      for (int it = 0; it < 8; it++) {
        int f = tid + it * 256;
        int half = f >> 10, r = (f >> 4) & 63, c = (f & 15) * 8;
        cp16(sb + K_OFF + buf * KSTAGE + half * KHALF + r * (AP_ * 2) + c * 2,
             (half ? Kl_g : Kh_g) + (size_t)((t + 2) * 64 + r) * DK_ + c);
      }
      asm volatile("cp.async.commit_group;" ::: "memory");
    }
    uint32_t KH = sb + K_OFF + (uint32_t)(t % 3) * KSTAGE;
    uint32_t KL = KH + KHALF;

    // Phase A: S[16 x 64] per warp = Q(m16) . K^T, split 3-term.
    float S[8][4];
#pragma unroll
    for (int i = 0; i < 8; i++)
#pragma unroll
      for (int q = 0; q < 4; q++) S[i][q] = 0.0f;

#pragma unroll
    for (int g = 0; g < 8; g++) {
#pragma unroll
      for (int np = 0; np < 4; np++) {
        uint32_t bhv[4], blv[4];
        uint32_t koff = (uint32_t)((np * 16 + ((lane >> 4) << 3) + (lane & 7)) * (AP_ * 2) +
                                   (g * 16 + (((lane >> 3) & 1) << 3)) * 2);
        ldsm4(bhv, KH + koff);
        ldsm4(blv, KL + koff);
        mma_group6(S[np * 2], S[np * 2 + 1], qh[g], ql[g], bhv, blv);
      }
    }

    // p = 2^S directly (bounded logits, no max subtraction needed).
    float sa = 0.0f, sb2 = 0.0f;
#pragma unroll
    for (int i = 0; i < 8; i++) {
      S[i][0] = ex2f_(S[i][0]);
      S[i][1] = ex2f_(S[i][1]);
      sa += S[i][0] + S[i][1];
      S[i][2] = ex2f_(S[i][2]);
      S[i][3] = ex2f_(S[i][3]);
      sb2 += S[i][2] + S[i][3];
    }
    sa += __shfl_xor_sync(0xffffffffu, sa, 1);
    sa += __shfl_xor_sync(0xffffffffu, sa, 2);
    sb2 += __shfl_xor_sync(0xffffffffu, sb2, 1);
    sb2 += __shfl_xor_sync(0xffffffffu, sb2, 2);
    l_a += sa;
    l_b += sb2;

    // Phase C: acc += P @ K (truncation-split P in regs, trans ldmatrix K).
#pragma unroll
    for (int g2 = 0; g2 < 4; g2++) {
      uint32_t pah[4], pal[4];
      trunc_split(S[2 * g2][0],     S[2 * g2][1],     pah[0], pal[0]);
      trunc_split(S[2 * g2][2],     S[2 * g2][3],     pah[1], pal[1]);
      trunc_split(S[2 * g2 + 1][0], S[2 * g2 + 1][1], pah[2], pal[2]);
      trunc_split(S[2 * g2 + 1][2], S[2 * g2 + 1][3], pah[3], pal[3]);
#pragma unroll
      for (int dp = 0; dp < 8; dp++) {
        uint32_t bhv[4], blv[4];
        uint32_t koff = (uint32_t)((g2 * 16 + (lane & 15)) * (AP_ * 2) +
                                   (dp * 16 + ((lane >> 4) << 3)) * 2);
        ldsm4t(bhv, KH + koff);
        ldsm4t(blv, KL + koff);
        mma_group6(acc[dp * 2], acc[dp * 2 + 1], pah, pal, bhv, blv);
      }
    }
  }

  float inva = 0.5f / l_a, invb = 0.5f / l_b;
  float* Z = (isQ ? g_Z1 : g_Z2) + (size_t)b * L_ * D_;
  int ra = r0 + w * 16 + (lane >> 2);
#pragma unroll
  for (int d = 0; d < 16; d++) {
    int col = head * DK_ + d * 8 + (lane & 3) * 2;
    float2 v0 = make_float2(acc[d][0] * inva, acc[d][1] * inva);
    float2 v1 = make_float2(acc[d][2] * invb, acc[d][3] * invb);
    *(float2*)&Z[(size_t)ra * D_ + col] = v0;
    *(float2*)&Z[(size_t)(ra + 8) * D_ + col] = v1;
  }
}

// ---------------------------------------------------------------------------
extern "C" void kernel_launch(void* const* d_in, const int* in_sizes, int n_in,
                              void* d_out, int out_size) {
  (void)in_sizes; (void)n_in; (void)out_size;
  const float* keys    = (const float*)d_in[0];
  const float* queries = (const float*)d_in[1];
  const float* values  = (const float*)d_in[2];
  const float* Wk      = (const float*)d_in[3];
  const float* Wq      = (const float*)d_in[4];
  const float* Wv      = (const float*)d_in[5];
  const float* Wu      = (const float*)d_in[6];
  const float* bu      = (const float*)d_in[7];
  float* out = (float*)d_out;

  cudaFuncSetAttribute(attn_mma, cudaFuncAttributeMaxDynamicSharedMemorySize,
                       ATTN_SMEM);
  cudaFuncSetAttribute(proj_mma2, cudaFuncAttributeMaxDynamicSharedMemorySize,
                       GEMM_SMEM);
  cudaFuncSetAttribute(final_mma2, cudaFuncAttributeMaxDynamicSharedMemorySize,
                       GEMM_SMEM);

  convert_all<<<(NCONV + 255) / 256, 256>>>(keys, queries, values, Wk, Wq, Wv, Wu);
  proj_mma2<<<dim3(16, 8, 12), 256, GEMM_SMEM>>>();
  attn_mma<<<dim3(32, 32), 256, ATTN_SMEM>>>();
  convert_zsum<<<NX4 / 256, 256>>>(NX4);
  final_mma2<<<dim3(8, 16, 4), 256, GEMM_SMEM>>>(bu, out);
}

// round 13
// speedup vs baseline: 1.0507x; 1.0035x over previous
#include <cuda_runtime.h>
#include <cuda_bf16.h>
#include <stdint.h>

// Shapes fixed by the problem: b=4, l=2048, d_model=1024, h=8, dk=128.
#define B_  4
#define L_  2048
#define D_  1024
#define H_  8
#define DK_ 128

// Pre-split inputs/weights (hi + residual lo bf16).
__device__ __nv_bfloat16 g_Xh[3 * B_ * L_ * D_];   // k/q/v inputs, [pj][b][t][d]
__device__ __nv_bfloat16 g_Xl[3 * B_ * L_ * D_];
__device__ __nv_bfloat16 g_Wh[4 * D_ * D_];        // Wk,Wq,Wv,Wu, [pj][c][d]
__device__ __nv_bfloat16 g_Wl[4 * D_ * D_];

// Projections, split bf16, channel-major Y[b][c][t]. Yq/Yv carry dk^-.5*log2e.
__device__ __nv_bfloat16 g_Ykh[B_ * D_ * L_];
__device__ __nv_bfloat16 g_Ykl[B_ * D_ * L_];
__device__ __nv_bfloat16 g_Yqh[B_ * D_ * L_];
__device__ __nv_bfloat16 g_Yql[B_ * D_ * L_];
__device__ __nv_bfloat16 g_Yvh[B_ * D_ * L_];
__device__ __nv_bfloat16 g_Yvl[B_ * D_ * L_];

// Attention outputs (fp32) and their summed split-bf16 form.
__device__ float g_Z1[B_ * L_ * D_];
__device__ float g_Z2[B_ * L_ * D_];
__device__ __nv_bfloat16 g_Zh[B_ * L_ * D_];
__device__ __nv_bfloat16 g_Zl[B_ * L_ * D_];

// ---------------------------------------------------------------------------
// Helpers
// ---------------------------------------------------------------------------
__device__ __forceinline__ uint32_t sptr(const void* p) {
  return (uint32_t)__cvta_generic_to_shared(p);
}

__device__ __forceinline__ void ldsm4(uint32_t r[4], uint32_t a) {
  asm volatile("ldmatrix.sync.aligned.m8n8.x4.shared.b16 {%0,%1,%2,%3}, [%4];"
               : "=r"(r[0]), "=r"(r[1]), "=r"(r[2]), "=r"(r[3]) : "r"(a));
}
__device__ __forceinline__ void ldsm4t(uint32_t r[4], uint32_t a) {
  asm volatile("ldmatrix.sync.aligned.m8n8.x4.trans.shared.b16 {%0,%1,%2,%3}, [%4];"
               : "=r"(r[0]), "=r"(r[1]), "=r"(r[2]), "=r"(r[3]) : "r"(a));
}

// NOTE: intentionally NON-volatile. Pure register function; letting the
// compiler/ptxas reorder MMAs against softmax ALU/MUFU work fills the
// tensor pipe's idle issue slots. Data deps (ldsm outputs, accumulators)
// preserve correctness ordering.
__device__ __forceinline__ void mma16816(float c[4], const uint32_t a[4],
                                         uint32_t b0, uint32_t b1) {
  asm("mma.sync.aligned.m16n8k16.row.col.f32.bf16.bf16.f32 "
      "{%0,%1,%2,%3},{%4,%5,%6,%7},{%8,%9},{%0,%1,%2,%3};\n"
      : "+f"(c[0]), "+f"(c[1]), "+f"(c[2]), "+f"(c[3])
      : "r"(a[0]), "r"(a[1]), "r"(a[2]), "r"(a[3]), "r"(b0), "r"(b1));
}

// 6-MMA split group with interleaved accumulator targets (breaks RAW chains).
__device__ __forceinline__ void mma_group6(float c0[4], float c1[4],
                                           const uint32_t ah[4], const uint32_t al[4],
                                           const uint32_t bh[4], const uint32_t bl[4]) {
  mma16816(c0, ah, bh[0], bh[1]);
  mma16816(c1, ah, bh[2], bh[3]);
  mma16816(c0, ah, bl[0], bl[1]);
  mma16816(c1, ah, bl[2], bl[3]);
  mma16816(c0, al, bh[0], bh[1]);
  mma16816(c1, al, bh[2], bh[3]);
}

// Round-to-nearest split (epilogues / converts).
__device__ __forceinline__ void split_pack(float x, float y, uint32_t& h, uint32_t& l) {
  __nv_bfloat162 H = __floats2bfloat162_rn(x, y);
  float hx = __bfloat162float(H.x), hy = __bfloat162float(H.y);
  __nv_bfloat162 Lo = __floats2bfloat162_rn(x - hx, y - hy);
  h = *reinterpret_cast<uint32_t*>(&H);
  l = *reinterpret_cast<uint32_t*>(&Lo);
}

// Cheap truncation split for NON-NEGATIVE values (softmax p): 6 ops.
__device__ __forceinline__ void trunc_split(float x, float y, uint32_t& h, uint32_t& l) {
  uint32_t xb = __float_as_uint(x), yb = __float_as_uint(y);
  h = __byte_perm(xb, yb, 0x7632);
  float xl = x - __uint_as_float(xb & 0xFFFF0000u);
  float yl = y - __uint_as_float(yb & 0xFFFF0000u);
  l = __byte_perm(__float_as_uint(xl), __float_as_uint(yl), 0x7632);
}

__device__ __forceinline__ float ex2f_(float x) {
  float y;
  asm("ex2.approx.ftz.f32 %0, %1;" : "=f"(y) : "f"(x));
  return y;
}

__device__ __forceinline__ void cp16(uint32_t dst, const void* src) {
  asm volatile("cp.async.cg.shared.global [%0], [%1], 16;" :: "r"(dst), "l"(src));
}

// ---------------------------------------------------------------------------
// Kernel 0a: ONE fused fp32 -> split-bf16 conversion over all 7 tensors.
// ---------------------------------------------------------------------------
#define NX4 ((B_ * L_ * D_) / 4)
#define NW4 ((D_ * D_) / 4)
#define NCONV (3 * NX4 + 4 * NW4)

__global__ void __launch_bounds__(256) convert_all(
    const float* __restrict__ k, const float* __restrict__ q,
    const float* __restrict__ v, const float* __restrict__ wk,
    const float* __restrict__ wq, const float* __restrict__ wv,
    const float* __restrict__ wu) {
  int i = blockIdx.x * 256 + threadIdx.x;
  if (i >= NCONV) return;
  const float* src;
  __nv_bfloat16 *dh, *dl;
  int local;
  if (i < 3 * NX4) {
    int which = i / NX4;
    local = i - which * NX4;
    src = (which == 0) ? k : (which == 1) ? q : v;
    dh = g_Xh + (size_t)which * (B_ * L_ * D_);
    dl = g_Xl + (size_t)which * (B_ * L_ * D_);
  } else {
    int j = i - 3 * NX4;
    int which = j / NW4;
    local = j - which * NW4;
    src = (which == 0) ? wk : (which == 1) ? wq : (which == 2) ? wv : wu;
    dh = g_Wh + (size_t)which * (D_ * D_);
    dl = g_Wl + (size_t)which * (D_ * D_);
  }
  float4 vv = reinterpret_cast<const float4*>(src)[local];
  uint32_t h0, l0, h1, l1;
  split_pack(vv.x, vv.y, h0, l0);
  split_pack(vv.z, vv.w, h1, l1);
  reinterpret_cast<uint32_t*>(dh)[local * 2]     = h0;
  reinterpret_cast<uint32_t*>(dh)[local * 2 + 1] = h1;
  reinterpret_cast<uint32_t*>(dl)[local * 2]     = l0;
  reinterpret_cast<uint32_t*>(dl)[local * 2 + 1] = l1;
}

// Kernel 0b: Zs = split(Z1 + Z2).
__global__ void __launch_bounds__(256) convert_zsum(int n4) {
  int i = blockIdx.x * 256 + threadIdx.x;
  if (i >= n4) return;
  float4 a = reinterpret_cast<const float4*>(g_Z1)[i];
  float4 b = reinterpret_cast<const float4*>(g_Z2)[i];
  float4 s = make_float4(a.x + b.x, a.y + b.y, a.z + b.z, a.w + b.w);
  uint32_t h0, l0, h1, l1;
  split_pack(s.x, s.y, h0, l0);
  split_pack(s.z, s.w, h1, l1);
  reinterpret_cast<uint32_t*>(g_Zh)[i * 2]     = h0;
  reinterpret_cast<uint32_t*>(g_Zh)[i * 2 + 1] = h1;
  reinterpret_cast<uint32_t*>(g_Zl)[i * 2]     = l0;
  reinterpret_cast<uint32_t*>(g_Zl)[i * 2 + 1] = l1;
}

// ---------------------------------------------------------------------------
// GEMM: 128x128 CTA tile, BK=32, pitch 40 bf16 (80 B), 2-stage cp.async ring,
// one __syncthreads per k-step. 80 KB smem -> 2 CTAs/SM (regs capped at 128).
// ---------------------------------------------------------------------------
#define GARR_B   10240                 // 128 rows * 80 B
#define GSTAGE_B (4 * GARR_B)          // 40960
#define GEMM_SMEM (2 * GSTAGE_B)       // 81920

struct GemmPtrs {
  const __nv_bfloat16 *Ah, *Al, *Bh, *Bl;
};

__device__ __forceinline__ void gemm_issue(
    const GemmPtrs& gp, uint32_t sb, int kc, int tid, int m0, int n0) {
  uint32_t stage = sb + (uint32_t)(kc & 1) * GSTAGE_B;
  int k0 = kc * 32;
  const __nv_bfloat16* ps[4] = {gp.Ah, gp.Al, gp.Bh, gp.Bl};
#pragma unroll
  for (int it = 0; it < 8; it++) {
    int f = tid + it * 256;            // 0..2047
    int arr = f >> 9, q = f & 511;     // 512 cp16 per array
    int r = q >> 2, c8 = (q & 3) * 8;  // row, bf16 col
    int row = (arr < 2 ? m0 : n0) + r;
    cp16(stage + (uint32_t)(arr * GARR_B + r * 80 + c8 * 2),
         ps[arr] + (size_t)row * D_ + k0 + c8);
  }
  asm volatile("cp.async.commit_group;" ::: "memory");
}

__device__ __forceinline__ void gemm_compute(
    float acc[2][8][4], uint32_t sb, int kc, int lane, int wm, int wn) {
  uint32_t stage = sb + (uint32_t)(kc & 1) * GSTAGE_B;
  uint32_t Ah_s = stage, Al_s = stage + GARR_B;
  uint32_t Bh_s = stage + 2 * GARR_B, Bl_s = stage + 3 * GARR_B;
#pragma unroll
  for (int g = 0; g < 2; g++) {
    uint32_t ah[2][4], al[2][4];
#pragma unroll
    for (int mi = 0; mi < 2; mi++) {
      uint32_t off = (uint32_t)((wm * 32 + mi * 16 + (lane & 15)) * 80 +
                                (g * 16 + ((lane >> 4) << 3)) * 2);
      ldsm4(ah[mi], Ah_s + off);
      ldsm4(al[mi], Al_s + off);
    }
#pragma unroll
    for (int np = 0; np < 4; np++) {
      uint32_t bhv[4], blv[4];
      uint32_t off = (uint32_t)((wn * 64 + np * 16 + ((lane >> 4) << 3) + (lane & 7)) * 80 +
                                (g * 16 + (((lane >> 3) & 1) << 3)) * 2);
      ldsm4(bhv, Bh_s + off);
      ldsm4(blv, Bl_s + off);
#pragma unroll
      for (int mi = 0; mi < 2; mi++)
        mma_group6(acc[mi][np * 2], acc[mi][np * 2 + 1], ah[mi], al[mi], bhv, blv);
    }
  }
}

// 2-stage mainloop, 32 k-steps: wait(t), bar, issue(t+1), compute(t).
__device__ __forceinline__ void gemm_mainloop(
    float acc[2][8][4], const GemmPtrs& gp, uint32_t sb, int tid, int lane,
    int wm, int wn, int m0, int n0) {
  gemm_issue(gp, sb, 0, tid, m0, n0);
  for (int t = 0; t < 32; t++) {
    asm volatile("cp.async.wait_group 0;" ::: "memory");
    __syncthreads();
    if (t + 1 < 32) gemm_issue(gp, sb, t + 1, tid, m0, n0);
    gemm_compute(acc, sb, t, lane, wm, wn);
  }
}

// ---------------------------------------------------------------------------
// Kernel 1: projections. Y[c][t] = W[c][:].X[t][:]; split-bf16 output * scl.
// ---------------------------------------------------------------------------
__global__ void __launch_bounds__(256, 2) proj_mma2() {
  extern __shared__ char smg[];
  uint32_t sb = sptr(smg);
  const float QS = 0.08838834764831845f * 1.4426950408889634f;

  int z = blockIdx.z, pj = z >> 2, b = z & 3;
  GemmPtrs gp;
  gp.Ah = g_Wh + (size_t)pj * (D_ * D_);
  gp.Al = g_Wl + (size_t)pj * (D_ * D_);
  gp.Bh = g_Xh + ((size_t)pj * B_ + b) * (L_ * D_);
  gp.Bl = g_Xl + ((size_t)pj * B_ + b) * (L_ * D_);
  __nv_bfloat16* Yh = ((pj == 0) ? g_Ykh : (pj == 1) ? g_Yqh : g_Yvh) + (size_t)b * D_ * L_;
  __nv_bfloat16* Yl = ((pj == 0) ? g_Ykl : (pj == 1) ? g_Yql : g_Yvl) + (size_t)b * D_ * L_;
  float scl = (pj == 0) ? 1.0f : QS;

  int m0 = blockIdx.y * 128, n0 = blockIdx.x * 128;
  int tid = threadIdx.x, lane = tid & 31, w = tid >> 5;
  int wm = w & 3, wn = w >> 2;

  float acc[2][8][4];
#pragma unroll
  for (int mi = 0; mi < 2; mi++)
#pragma unroll
    for (int t8 = 0; t8 < 8; t8++)
#pragma unroll
      for (int q = 0; q < 4; q++) acc[mi][t8][q] = 0.0f;

  gemm_mainloop(acc, gp, sb, tid, lane, wm, wn, m0, n0);

#pragma unroll
  for (int mi = 0; mi < 2; mi++)
#pragma unroll
    for (int t8 = 0; t8 < 8; t8++) {
      int row = m0 + wm * 32 + mi * 16 + (lane >> 2);
      int col = n0 + wn * 64 + t8 * 8 + (lane & 3) * 2;
      uint32_t h, l;
      split_pack(acc[mi][t8][0] * scl, acc[mi][t8][1] * scl, h, l);
      *(uint32_t*)&Yh[(size_t)row * L_ + col] = h;
      *(uint32_t*)&Yl[(size_t)row * L_ + col] = l;
      split_pack(acc[mi][t8][2] * scl, acc[mi][t8][3] * scl, h, l);
      *(uint32_t*)&Yh[(size_t)(row + 8) * L_ + col] = h;
      *(uint32_t*)&Yl[(size_t)(row + 8) * L_ + col] = l;
    }
}

// ---------------------------------------------------------------------------
// Kernel 3: output projection. out[t][n] = Zs[t][:].Wu[n][:] + bu[n].
// ---------------------------------------------------------------------------
__global__ void __launch_bounds__(256, 2) final_mma2(const float* __restrict__ bu,
                                                     float* __restrict__ out) {
  extern __shared__ char smg[];
  uint32_t sb = sptr(smg);

  int b = blockIdx.z;
  GemmPtrs gp;
  gp.Ah = g_Zh + (size_t)b * (L_ * D_);
  gp.Al = g_Zl + (size_t)b * (L_ * D_);
  gp.Bh = g_Wh + (size_t)3 * (D_ * D_);
  gp.Bl = g_Wl + (size_t)3 * (D_ * D_);

  int m0 = blockIdx.y * 128, n0 = blockIdx.x * 128;
  int tid = threadIdx.x, lane = tid & 31, w = tid >> 5;
  int wm = w & 3, wn = w >> 2;

  float acc[2][8][4];
#pragma unroll
  for (int mi = 0; mi < 2; mi++)
#pragma unroll
    for (int t8 = 0; t8 < 8; t8++)
#pragma unroll
      for (int q = 0; q < 4; q++) acc[mi][t8][q] = 0.0f;

  gemm_mainloop(acc, gp, sb, tid, lane, wm, wn, m0, n0);

  float* Cb = out + (size_t)b * L_ * D_;
#pragma unroll
  for (int mi = 0; mi < 2; mi++)
#pragma unroll
    for (int t8 = 0; t8 < 8; t8++) {
      int row = m0 + wm * 32 + mi * 16 + (lane >> 2);
      int col = n0 + wn * 64 + t8 * 8 + (lane & 3) * 2;
      float2 bias = *(const float2*)&bu[col];
      float2 v0 = make_float2(acc[mi][t8][0] + bias.x, acc[mi][t8][1] + bias.y);
      float2 v1 = make_float2(acc[mi][t8][2] + bias.x, acc[mi][t8][3] + bias.y);
      *(float2*)&Cb[(size_t)row * D_ + col] = v0;
      *(float2*)&Cb[(size_t)(row + 8) * D_ + col] = v1;
    }
}

// ---------------------------------------------------------------------------
// Kernel 2: fused dual flash attention. 256 threads / 8 warps (m16 each),
// BN=64 keys/tile, 3-stage K ring, one __syncthreads per tile.
// Q fragments hoisted (loop-invariant). No-max softmax. Per tile, softmax and
// Phase C are split into two independent 32-key halves so the scheduler can
// overlap MUFU/ALU softmax work with tensor MMAs; the l reduction shuffles
// are deferred to after the tile loop (sum is linear).
// ---------------------------------------------------------------------------
#define AP_      136
#define QH_OFF   0
#define QL_OFF   (128 * AP_ * 2)
#define K_OFF    (2 * 128 * AP_ * 2)       // 69632
#define KHALF    (64 * AP_ * 2)            // 17408
#define KSTAGE   (2 * KHALF)               // 34816
#define ATTN_SMEM (K_OFF + 3 * KSTAGE)     // 174080

__global__ void __launch_bounds__(256, 1) attn_mma() {
  extern __shared__ char smc[];
  uint32_t sb = sptr(smc);

  int bh = blockIdx.y, b = bh >> 3, head = bh & 7;
  int xb = blockIdx.x;
  bool isQ = (xb < 16);
  int r0 = (isQ ? xb : xb - 16) * 128;

  size_t hb = (size_t)(b * D_ + head * DK_) * L_;
  const __nv_bfloat16* Qh_g = (isQ ? g_Yqh : g_Yvh) + hb + (size_t)r0 * DK_;
  const __nv_bfloat16* Ql_g = (isQ ? g_Yql : g_Yvl) + hb + (size_t)r0 * DK_;
  const __nv_bfloat16* Kh_g = g_Ykh + hb;
  const __nv_bfloat16* Kl_g = g_Ykl + hb;

  int tid = threadIdx.x, lane = tid & 31, w = tid >> 5;

  // Prologue: group0 = Q(hi+lo) + K tile 0; group1 = K tile 1.
#pragma unroll
  for (int it = 0; it < 16; it++) {
    int f = tid + it * 256;
    int half = f >> 11, r = (f >> 4) & 127, c = (f & 15) * 8;
    cp16(sb + (half ? QL_OFF : QH_OFF) + r * (AP_ * 2) + c * 2,
         (half ? Ql_g : Qh_g) + (size_t)r * DK_ + c);
  }
#pragma unroll
  for (int it = 0; it < 8; it++) {
    int f = tid + it * 256;
    int half = f >> 10, r = (f >> 4) & 63, c = (f & 15) * 8;
    cp16(sb + K_OFF + half * KHALF + r * (AP_ * 2) + c * 2,
         (half ? Kl_g : Kh_g) + (size_t)r * DK_ + c);
  }
  asm volatile("cp.async.commit_group;" ::: "memory");
#pragma unroll
  for (int it = 0; it < 8; it++) {
    int f = tid + it * 256;
    int half = f >> 10, r = (f >> 4) & 63, c = (f & 15) * 8;
    cp16(sb + K_OFF + KSTAGE + half * KHALF + r * (AP_ * 2) + c * 2,
         (half ? Kl_g : Kh_g) + (size_t)(64 + r) * DK_ + c);
  }
  asm volatile("cp.async.commit_group;" ::: "memory");

  // Q fragments are loop-invariant: load them once.
  asm volatile("cp.async.wait_group 1;" ::: "memory");
  __syncthreads();
  uint32_t qh[8][4], ql[8][4];
#pragma unroll
  for (int g = 0; g < 8; g++) {
    uint32_t qoff = (uint32_t)((w * 16 + (lane & 15)) * (AP_ * 2) +
                               (g * 16 + ((lane >> 4) << 3)) * 2);
    ldsm4(qh[g], sb + QH_OFF + qoff);
    ldsm4(ql[g], sb + QL_OFF + qoff);
  }

  float acc[16][4];
#pragma unroll
  for (int d = 0; d < 16; d++)
#pragma unroll
    for (int q = 0; q < 4; q++) acc[d][q] = 0.0f;
  float l_a = 0.0f, l_b = 0.0f;   // lane-local partial sums; reduced after loop

  for (int t = 0; t < 32; t++) {
    if (t < 31) asm volatile("cp.async.wait_group 1;" ::: "memory");
    else        asm volatile("cp.async.wait_group 0;" ::: "memory");
    __syncthreads();
    if (t + 2 < 32) {
      int buf = (t + 2) % 3;
#pragma unroll
      for (int it = 0; it < 8; it++) {
        int f = tid + it * 256;
        int half = f >> 10, r = (f >> 4) & 63, c = (f & 15) * 8;
        cp16(sb + K_OFF + buf * KSTAGE + half * KHALF + r * (AP_ * 2) + c * 2,
             (half ? Kl_g : Kh_g) + (size_t)((t + 2) * 64 + r) * DK_ + c);
      }
      asm volatile("cp.async.commit_group;" ::: "memory");
    }
    uint32_t KH = sb + K_OFF + (uint32_t)(t % 3) * KSTAGE;
    uint32_t KL = KH + KHALF;

    // Phase A: S[16 x 64] per warp = Q(m16) . K^T, split 3-term.
    float S[8][4];
#pragma unroll
    for (int i = 0; i < 8; i++)
#pragma unroll
      for (int q = 0; q < 4; q++) S[i][q] = 0.0f;

#pragma unroll
    for (int g = 0; g < 8; g++) {
#pragma unroll
      for (int np = 0; np < 4; np++) {
        uint32_t bhv[4], blv[4];
        uint32_t koff = (uint32_t)((np * 16 + ((lane >> 4) << 3) + (lane & 7)) * (AP_ * 2) +
                                   (g * 16 + (((lane >> 3) & 1) << 3)) * 2);
        ldsm4(bhv, KH + koff);
        ldsm4(blv, KL + koff);
        mma_group6(S[np * 2], S[np * 2 + 1], qh[g], ql[g], bhv, blv);
      }
    }

    // Two independent 32-key halves: softmax(Hx) can overlap Phase-C MMAs
    // of the other half in the scheduler (mma asm is non-volatile).
#pragma unroll
    for (int h2 = 0; h2 < 2; h2++) {
      // Softmax numerator for this half: p = 2^S (bounded logits, no max).
#pragma unroll
      for (int i = 4 * h2; i < 4 * h2 + 4; i++) {
        S[i][0] = ex2f_(S[i][0]);
        S[i][1] = ex2f_(S[i][1]);
        l_a += S[i][0] + S[i][1];
        S[i][2] = ex2f_(S[i][2]);
        S[i][3] = ex2f_(S[i][3]);
        l_b += S[i][2] + S[i][3];
      }
      // Phase C for this half: acc += P @ K.
#pragma unroll
      for (int gg = 0; gg < 2; gg++) {
        int g2 = h2 * 2 + gg;
        uint32_t pah[4], pal[4];
        trunc_split(S[2 * g2][0],     S[2 * g2][1],     pah[0], pal[0]);
        trunc_split(S[2 * g2][2],     S[2 * g2][3],     pah[1], pal[1]);
        trunc_split(S[2 * g2 + 1][0], S[2 * g2 + 1][1], pah[2], pal[2]);
        trunc_split(S[2 * g2 + 1][2], S[2 * g2 + 1][3], pah[3], pal[3]);
#pragma unroll
        for (int dp = 0; dp < 8; dp++) {
          uint32_t bhv[4], blv[4];
          uint32_t koff = (uint32_t)((g2 * 16 + (lane & 15)) * (AP_ * 2) +
                                     (dp * 16 + ((lane >> 4) << 3)) * 2);
          ldsm4t(bhv, KH + koff);
          ldsm4t(blv, KL + koff);
          mma_group6(acc[dp * 2], acc[dp * 2 + 1], pah, pal, bhv, blv);
        }
      }
    }
  }

  // Deferred l reduction (once, not per tile).
  l_a += __shfl_xor_sync(0xffffffffu, l_a, 1);
  l_a += __shfl_xor_sync(0xffffffffu, l_a, 2);
  l_b += __shfl_xor_sync(0xffffffffu, l_b, 1);
  l_b += __shfl_xor_sync(0xffffffffu, l_b, 2);

  float inva = 0.5f / l_a, invb = 0.5f / l_b;
  float* Z = (isQ ? g_Z1 : g_Z2) + (size_t)b * L_ * D_;
  int ra = r0 + w * 16 + (lane >> 2);
#pragma unroll
  for (int d = 0; d < 16; d++) {
    int col = head * DK_ + d * 8 + (lane & 3) * 2;
    float2 v0 = make_float2(acc[d][0] * inva, acc[d][1] * inva);
    float2 v1 = make_float2(acc[d][2] * invb, acc[d][3] * invb);
    *(float2*)&Z[(size_t)ra * D_ + col] = v0;
    *(float2*)&Z[(size_t)(ra + 8) * D_ + col] = v1;
  }
}

// ---------------------------------------------------------------------------
extern "C" void kernel_launch(void* const* d_in, const int* in_sizes, int n_in,
                              void* d_out, int out_size) {
  (void)in_sizes; (void)n_in; (void)out_size;
  const float* keys    = (const float*)d_in[0];
  const float* queries = (const float*)d_in[1];
  const float* values  = (const float*)d_in[2];
  const float* Wk      = (const float*)d_in[3];
  const float* Wq      = (const float*)d_in[4];
  const float* Wv      = (const float*)d_in[5];
  const float* Wu      = (const float*)d_in[6];
  const float* bu      = (const float*)d_in[7];
  float* out = (float*)d_out;

  cudaFuncSetAttribute(attn_mma, cudaFuncAttributeMaxDynamicSharedMemorySize,
                       ATTN_SMEM);
  cudaFuncSetAttribute(proj_mma2, cudaFuncAttributeMaxDynamicSharedMemorySize,
                       GEMM_SMEM);
  cudaFuncSetAttribute(final_mma2, cudaFuncAttributeMaxDynamicSharedMemorySize,
                       GEMM_SMEM);

  convert_all<<<(NCONV + 255) / 256, 256>>>(keys, queries, values, Wk, Wq, Wv, Wu);
  proj_mma2<<<dim3(16, 8, 12), 256, GEMM_SMEM>>>();
  attn_mma<<<dim3(32, 32), 256, ATTN_SMEM>>>();
  convert_zsum<<<NX4 / 256, 256>>>(NX4);
  final_mma2<<<dim3(8, 16, 4), 256, GEMM_SMEM>>>(bu, out);
}

// round 14
// speedup vs baseline: 1.0530x; 1.0022x over previous
#include <cuda_runtime.h>
#include <cuda_bf16.h>
#include <stdint.h>

// Shapes fixed by the problem: b=4, l=2048, d_model=1024, h=8, dk=128.
#define B_  4
#define L_  2048
#define D_  1024
#define H_  8
#define DK_ 128

// Pre-split inputs/weights (hi + residual lo bf16).
__device__ __nv_bfloat16 g_Xh[3 * B_ * L_ * D_];   // k/q/v inputs, [pj][b][t][d]
__device__ __nv_bfloat16 g_Xl[3 * B_ * L_ * D_];
__device__ __nv_bfloat16 g_Wh[4 * D_ * D_];        // Wk,Wq,Wv,Wu, [pj][c][d]
__device__ __nv_bfloat16 g_Wl[4 * D_ * D_];

// Projections, split bf16, channel-major Y[b][c][t]. Yq/Yv carry dk^-.5*log2e.
__device__ __nv_bfloat16 g_Ykh[B_ * D_ * L_];
__device__ __nv_bfloat16 g_Ykl[B_ * D_ * L_];
__device__ __nv_bfloat16 g_Yqh[B_ * D_ * L_];
__device__ __nv_bfloat16 g_Yql[B_ * D_ * L_];
__device__ __nv_bfloat16 g_Yvh[B_ * D_ * L_];
__device__ __nv_bfloat16 g_Yvl[B_ * D_ * L_];

// Attention outputs (fp32) and their summed split-bf16 form.
__device__ float g_Z1[B_ * L_ * D_];
__device__ float g_Z2[B_ * L_ * D_];
__device__ __nv_bfloat16 g_Zh[B_ * L_ * D_];
__device__ __nv_bfloat16 g_Zl[B_ * L_ * D_];

// ---------------------------------------------------------------------------
// Helpers
// ---------------------------------------------------------------------------
__device__ __forceinline__ uint32_t sptr(const void* p) {
  return (uint32_t)__cvta_generic_to_shared(p);
}

__device__ __forceinline__ void ldsm4(uint32_t r[4], uint32_t a) {
  asm volatile("ldmatrix.sync.aligned.m8n8.x4.shared.b16 {%0,%1,%2,%3}, [%4];"
               : "=r"(r[0]), "=r"(r[1]), "=r"(r[2]), "=r"(r[3]) : "r"(a));
}
__device__ __forceinline__ void ldsm4t(uint32_t r[4], uint32_t a) {
  asm volatile("ldmatrix.sync.aligned.m8n8.x4.trans.shared.b16 {%0,%1,%2,%3}, [%4];"
               : "=r"(r[0]), "=r"(r[1]), "=r"(r[2]), "=r"(r[3]) : "r"(a));
}

// Non-volatile on purpose: pure register op; lets ptxas interleave MMAs with
// softmax ALU/MUFU. Data dependencies preserve correctness.
__device__ __forceinline__ void mma16816(float c[4], const uint32_t a[4],
                                         uint32_t b0, uint32_t b1) {
  asm("mma.sync.aligned.m16n8k16.row.col.f32.bf16.bf16.f32 "
      "{%0,%1,%2,%3},{%4,%5,%6,%7},{%8,%9},{%0,%1,%2,%3};\n"
      : "+f"(c[0]), "+f"(c[1]), "+f"(c[2]), "+f"(c[3])
      : "r"(a[0]), "r"(a[1]), "r"(a[2]), "r"(a[3]), "r"(b0), "r"(b1));
}

// 6-MMA split group with interleaved accumulator targets (breaks RAW chains).
__device__ __forceinline__ void mma_group6(float c0[4], float c1[4],
                                           const uint32_t ah[4], const uint32_t al[4],
                                           const uint32_t bh[4], const uint32_t bl[4]) {
  mma16816(c0, ah, bh[0], bh[1]);
  mma16816(c1, ah, bh[2], bh[3]);
  mma16816(c0, ah, bl[0], bl[1]);
  mma16816(c1, ah, bl[2], bl[3]);
  mma16816(c0, al, bh[0], bh[1]);
  mma16816(c1, al, bh[2], bh[3]);
}

// Round-to-nearest split (epilogues / converts).
__device__ __forceinline__ void split_pack(float x, float y, uint32_t& h, uint32_t& l) {
  __nv_bfloat162 H = __floats2bfloat162_rn(x, y);
  float hx = __bfloat162float(H.x), hy = __bfloat162float(H.y);
  __nv_bfloat162 Lo = __floats2bfloat162_rn(x - hx, y - hy);
  h = *reinterpret_cast<uint32_t*>(&H);
  l = *reinterpret_cast<uint32_t*>(&Lo);
}

// Cheap truncation split for NON-NEGATIVE values (softmax p): 6 ops.
__device__ __forceinline__ void trunc_split(float x, float y, uint32_t& h, uint32_t& l) {
  uint32_t xb = __float_as_uint(x), yb = __float_as_uint(y);
  h = __byte_perm(xb, yb, 0x7632);
  float xl = x - __uint_as_float(xb & 0xFFFF0000u);
  float yl = y - __uint_as_float(yb & 0xFFFF0000u);
  l = __byte_perm(__float_as_uint(xl), __float_as_uint(yl), 0x7632);
}

__device__ __forceinline__ float ex2f_(float x) {
  float y;
  asm("ex2.approx.ftz.f32 %0, %1;" : "=f"(y) : "f"(x));
  return y;
}

__device__ __forceinline__ void cp16(uint32_t dst, const void* src) {
  asm volatile("cp.async.cg.shared.global [%0], [%1], 16;" :: "r"(dst), "l"(src));
}

// ---------------------------------------------------------------------------
// Kernel 0a: ONE fused fp32 -> split-bf16 conversion over all 7 tensors.
// ---------------------------------------------------------------------------
#define NX4 ((B_ * L_ * D_) / 4)
#define NW4 ((D_ * D_) / 4)
#define NCONV (3 * NX4 + 4 * NW4)

__global__ void __launch_bounds__(256) convert_all(
    const float* __restrict__ k, const float* __restrict__ q,
    const float* __restrict__ v, const float* __restrict__ wk,
    const float* __restrict__ wq, const float* __restrict__ wv,
    const float* __restrict__ wu) {
  int i = blockIdx.x * 256 + threadIdx.x;
  if (i >= NCONV) return;
  const float* src;
  __nv_bfloat16 *dh, *dl;
  int local;
  if (i < 3 * NX4) {
    int which = i / NX4;
    local = i - which * NX4;
    src = (which == 0) ? k : (which == 1) ? q : v;
    dh = g_Xh + (size_t)which * (B_ * L_ * D_);
    dl = g_Xl + (size_t)which * (B_ * L_ * D_);
  } else {
    int j = i - 3 * NX4;
    int which = j / NW4;
    local = j - which * NW4;
    src = (which == 0) ? wk : (which == 1) ? wq : (which == 2) ? wv : wu;
    dh = g_Wh + (size_t)which * (D_ * D_);
    dl = g_Wl + (size_t)which * (D_ * D_);
  }
  float4 vv = reinterpret_cast<const float4*>(src)[local];
  uint32_t h0, l0, h1, l1;
  split_pack(vv.x, vv.y, h0, l0);
  split_pack(vv.z, vv.w, h1, l1);
  reinterpret_cast<uint32_t*>(dh)[local * 2]     = h0;
  reinterpret_cast<uint32_t*>(dh)[local * 2 + 1] = h1;
  reinterpret_cast<uint32_t*>(dl)[local * 2]     = l0;
  reinterpret_cast<uint32_t*>(dl)[local * 2 + 1] = l1;
}

// Kernel 0b: Zs = split(Z1 + Z2).
__global__ void __launch_bounds__(256) convert_zsum(int n4) {
  int i = blockIdx.x * 256 + threadIdx.x;
  if (i >= n4) return;
  float4 a = reinterpret_cast<const float4*>(g_Z1)[i];
  float4 b = reinterpret_cast<const float4*>(g_Z2)[i];
  float4 s = make_float4(a.x + b.x, a.y + b.y, a.z + b.z, a.w + b.w);
  uint32_t h0, l0, h1, l1;
  split_pack(s.x, s.y, h0, l0);
  split_pack(s.z, s.w, h1, l1);
  reinterpret_cast<uint32_t*>(g_Zh)[i * 2]     = h0;
  reinterpret_cast<uint32_t*>(g_Zh)[i * 2 + 1] = h1;
  reinterpret_cast<uint32_t*>(g_Zl)[i * 2]     = l0;
  reinterpret_cast<uint32_t*>(g_Zl)[i * 2 + 1] = l1;
}

// ---------------------------------------------------------------------------
// GEMM: 128x128 CTA tile, BK=32, pitch 40 bf16 (80 B), 2-stage cp.async ring,
// one __syncthreads per k-step. 80 KB smem -> 2 CTAs/SM (regs capped at 128).
// ---------------------------------------------------------------------------
#define GARR_B   10240                 // 128 rows * 80 B
#define GSTAGE_B (4 * GARR_B)          // 40960
#define GEMM_SMEM (2 * GSTAGE_B)       // 81920

struct GemmPtrs {
  const __nv_bfloat16 *Ah, *Al, *Bh, *Bl;
};

__device__ __forceinline__ void gemm_issue(
    const GemmPtrs& gp, uint32_t sb, int kc, int tid, int m0, int n0) {
  uint32_t stage = sb + (uint32_t)(kc & 1) * GSTAGE_B;
  int k0 = kc * 32;
  const __nv_bfloat16* ps[4] = {gp.Ah, gp.Al, gp.Bh, gp.Bl};
#pragma unroll
  for (int it = 0; it < 8; it++) {
    int f = tid + it * 256;            // 0..2047
    int arr = f >> 9, q = f & 511;     // 512 cp16 per array
    int r = q >> 2, c8 = (q & 3) * 8;  // row, bf16 col
    int row = (arr < 2 ? m0 : n0) + r;
    cp16(stage + (uint32_t)(arr * GARR_B + r * 80 + c8 * 2),
         ps[arr] + (size_t)row * D_ + k0 + c8);
  }
  asm volatile("cp.async.commit_group;" ::: "memory");
}

__device__ __forceinline__ void gemm_compute(
    float acc[2][8][4], uint32_t sb, int kc, int lane, int wm, int wn) {
  uint32_t stage = sb + (uint32_t)(kc & 1) * GSTAGE_B;
  uint32_t Ah_s = stage, Al_s = stage + GARR_B;
  uint32_t Bh_s = stage + 2 * GARR_B, Bl_s = stage + 3 * GARR_B;
#pragma unroll
  for (int g = 0; g < 2; g++) {
    uint32_t ah[2][4], al[2][4];
#pragma unroll
    for (int mi = 0; mi < 2; mi++) {
      uint32_t off = (uint32_t)((wm * 32 + mi * 16 + (lane & 15)) * 80 +
                                (g * 16 + ((lane >> 4) << 3)) * 2);
      ldsm4(ah[mi], Ah_s + off);
      ldsm4(al[mi], Al_s + off);
    }
#pragma unroll
    for (int np = 0; np < 4; np++) {
      uint32_t bhv[4], blv[4];
      uint32_t off = (uint32_t)((wn * 64 + np * 16 + ((lane >> 4) << 3) + (lane & 7)) * 80 +
                                (g * 16 + (((lane >> 3) & 1) << 3)) * 2);
      ldsm4(bhv, Bh_s + off);
      ldsm4(blv, Bl_s + off);
#pragma unroll
      for (int mi = 0; mi < 2; mi++)
        mma_group6(acc[mi][np * 2], acc[mi][np * 2 + 1], ah[mi], al[mi], bhv, blv);
    }
  }
}

// 2-stage mainloop, 32 k-steps: wait(t), bar, issue(t+1), compute(t).
__device__ __forceinline__ void gemm_mainloop(
    float acc[2][8][4], const GemmPtrs& gp, uint32_t sb, int tid, int lane,
    int wm, int wn, int m0, int n0) {
  gemm_issue(gp, sb, 0, tid, m0, n0);
  for (int t = 0; t < 32; t++) {
    asm volatile("cp.async.wait_group 0;" ::: "memory");
    __syncthreads();
    if (t + 1 < 32) gemm_issue(gp, sb, t + 1, tid, m0, n0);
    gemm_compute(acc, sb, t, lane, wm, wn);
  }
}

// ---------------------------------------------------------------------------
// Kernel 1: projections. Y[c][t] = W[c][:].X[t][:]; split-bf16 output * scl.
// ---------------------------------------------------------------------------
__global__ void __launch_bounds__(256, 2) proj_mma2() {
  extern __shared__ char smg[];
  uint32_t sb = sptr(smg);
  const float QS = 0.08838834764831845f * 1.4426950408889634f;

  int z = blockIdx.z, pj = z >> 2, b = z & 3;
  GemmPtrs gp;
  gp.Ah = g_Wh + (size_t)pj * (D_ * D_);
  gp.Al = g_Wl + (size_t)pj * (D_ * D_);
  gp.Bh = g_Xh + ((size_t)pj * B_ + b) * (L_ * D_);
  gp.Bl = g_Xl + ((size_t)pj * B_ + b) * (L_ * D_);
  __nv_bfloat16* Yh = ((pj == 0) ? g_Ykh : (pj == 1) ? g_Yqh : g_Yvh) + (size_t)b * D_ * L_;
  __nv_bfloat16* Yl = ((pj == 0) ? g_Ykl : (pj == 1) ? g_Yql : g_Yvl) + (size_t)b * D_ * L_;
  float scl = (pj == 0) ? 1.0f : QS;

  int m0 = blockIdx.y * 128, n0 = blockIdx.x * 128;
  int tid = threadIdx.x, lane = tid & 31, w = tid >> 5;
  int wm = w & 3, wn = w >> 2;

  float acc[2][8][4];
#pragma unroll
  for (int mi = 0; mi < 2; mi++)
#pragma unroll
    for (int t8 = 0; t8 < 8; t8++)
#pragma unroll
      for (int q = 0; q < 4; q++) acc[mi][t8][q] = 0.0f;

  gemm_mainloop(acc, gp, sb, tid, lane, wm, wn, m0, n0);

#pragma unroll
  for (int mi = 0; mi < 2; mi++)
#pragma unroll
    for (int t8 = 0; t8 < 8; t8++) {
      int row = m0 + wm * 32 + mi * 16 + (lane >> 2);
      int col = n0 + wn * 64 + t8 * 8 + (lane & 3) * 2;
      uint32_t h, l;
      split_pack(acc[mi][t8][0] * scl, acc[mi][t8][1] * scl, h, l);
      *(uint32_t*)&Yh[(size_t)row * L_ + col] = h;
      *(uint32_t*)&Yl[(size_t)row * L_ + col] = l;
      split_pack(acc[mi][t8][2] * scl, acc[mi][t8][3] * scl, h, l);
      *(uint32_t*)&Yh[(size_t)(row + 8) * L_ + col] = h;
      *(uint32_t*)&Yl[(size_t)(row + 8) * L_ + col] = l;
    }
}

// ---------------------------------------------------------------------------
// Kernel 3: output projection. out[t][n] = Zs[t][:].Wu[n][:] + bu[n].
// ---------------------------------------------------------------------------
__global__ void __launch_bounds__(256, 2) final_mma2(const float* __restrict__ bu,
                                                     float* __restrict__ out) {
  extern __shared__ char smg[];
  uint32_t sb = sptr(smg);

  int b = blockIdx.z;
  GemmPtrs gp;
  gp.Ah = g_Zh + (size_t)b * (L_ * D_);
  gp.Al = g_Zl + (size_t)b * (L_ * D_);
  gp.Bh = g_Wh + (size_t)3 * (D_ * D_);
  gp.Bl = g_Wl + (size_t)3 * (D_ * D_);

  int m0 = blockIdx.y * 128, n0 = blockIdx.x * 128;
  int tid = threadIdx.x, lane = tid & 31, w = tid >> 5;
  int wm = w & 3, wn = w >> 2;

  float acc[2][8][4];
#pragma unroll
  for (int mi = 0; mi < 2; mi++)
#pragma unroll
    for (int t8 = 0; t8 < 8; t8++)
#pragma unroll
      for (int q = 0; q < 4; q++) acc[mi][t8][q] = 0.0f;

  gemm_mainloop(acc, gp, sb, tid, lane, wm, wn, m0, n0);

  float* Cb = out + (size_t)b * L_ * D_;
#pragma unroll
  for (int mi = 0; mi < 2; mi++)
#pragma unroll
    for (int t8 = 0; t8 < 8; t8++) {
      int row = m0 + wm * 32 + mi * 16 + (lane >> 2);
      int col = n0 + wn * 64 + t8 * 8 + (lane & 3) * 2;
      float2 bias = *(const float2*)&bu[col];
      float2 v0 = make_float2(acc[mi][t8][0] + bias.x, acc[mi][t8][1] + bias.y);
      float2 v1 = make_float2(acc[mi][t8][2] + bias.x, acc[mi][t8][3] + bias.y);
      *(float2*)&Cb[(size_t)row * D_ + col] = v0;
      *(float2*)&Cb[(size_t)(row + 8) * D_ + col] = v1;
    }
}

// ---------------------------------------------------------------------------
// Kernel 2: fused dual flash attention. 256 threads / 8 warps (m16 each).
// 2-stage ring of 128-key MEGA-tiles (two 64-key sub-tiles per barrier
// window): 16 barrier windows instead of 32. Q fragments hoisted.
// No-max softmax, deferred l reduction, split-3 bf16 MMA core.
// ---------------------------------------------------------------------------
#define AP_      136
#define QH_OFF   0
#define QL_OFF   (128 * AP_ * 2)
#define K_OFF    (2 * 128 * AP_ * 2)       // 69632
#define KHALF2   (128 * AP_ * 2)           // 34816 (128 rows hi or lo)
#define KSTG2    (2 * KHALF2)              // 69632 per mega-stage
#define ATTN_SMEM (K_OFF + 2 * KSTG2)      // 208896

__global__ void __launch_bounds__(256, 1) attn_mma() {
  extern __shared__ char smc[];
  uint32_t sb = sptr(smc);

  int bh = blockIdx.y, b = bh >> 3, head = bh & 7;
  int xb = blockIdx.x;
  bool isQ = (xb < 16);
  int r0 = (isQ ? xb : xb - 16) * 128;

  size_t hb = (size_t)(b * D_ + head * DK_) * L_;
  const __nv_bfloat16* Qh_g = (isQ ? g_Yqh : g_Yvh) + hb + (size_t)r0 * DK_;
  const __nv_bfloat16* Ql_g = (isQ ? g_Yql : g_Yvl) + hb + (size_t)r0 * DK_;
  const __nv_bfloat16* Kh_g = g_Ykh + hb;
  const __nv_bfloat16* Kl_g = g_Ykl + hb;

  int tid = threadIdx.x, lane = tid & 31, w = tid >> 5;

  // Prologue: one group = Q (hi+lo) + mega-stage 0 (keys 0..127, hi+lo).
#pragma unroll
  for (int it = 0; it < 16; it++) {
    int f = tid + it * 256;
    int half = f >> 11, r = (f >> 4) & 127, c = (f & 15) * 8;
    cp16(sb + (half ? QL_OFF : QH_OFF) + r * (AP_ * 2) + c * 2,
         (half ? Ql_g : Qh_g) + (size_t)r * DK_ + c);
  }
#pragma unroll
  for (int it = 0; it < 16; it++) {
    int f = tid + it * 256;                // 0..4095
    int half = f >> 11, r = (f >> 4) & 127, c = (f & 15) * 8;
    cp16(sb + K_OFF + half * KHALF2 + r * (AP_ * 2) + c * 2,
         (half ? Kl_g : Kh_g) + (size_t)r * DK_ + c);
  }
  asm volatile("cp.async.commit_group;" ::: "memory");
  asm volatile("cp.async.wait_group 0;" ::: "memory");
  __syncthreads();

  // Q fragments are loop-invariant: load them once.
  uint32_t qh[8][4], ql[8][4];
#pragma unroll
  for (int g = 0; g < 8; g++) {
    uint32_t qoff = (uint32_t)((w * 16 + (lane & 15)) * (AP_ * 2) +
                               (g * 16 + ((lane >> 4) << 3)) * 2);
    ldsm4(qh[g], sb + QH_OFF + qoff);
    ldsm4(ql[g], sb + QL_OFF + qoff);
  }

  float acc[16][4];
#pragma unroll
  for (int d = 0; d < 16; d++)
#pragma unroll
    for (int q = 0; q < 4; q++) acc[d][q] = 0.0f;
  float l_a = 0.0f, l_b = 0.0f;   // lane-local partials; reduced after loop

  for (int T = 0; T < 16; T++) {
    // Overlap next mega-tile's load with this one's compute.
    if (T + 1 < 16) {
      uint32_t dstb = sb + K_OFF + (uint32_t)((T + 1) & 1) * KSTG2;
#pragma unroll
      for (int it = 0; it < 16; it++) {
        int f = tid + it * 256;
        int half = f >> 11, r = (f >> 4) & 127, c = (f & 15) * 8;
        cp16(dstb + half * KHALF2 + r * (AP_ * 2) + c * 2,
             (half ? Kl_g : Kh_g) + (size_t)((T + 1) * 128 + r) * DK_ + c);
      }
      asm volatile("cp.async.commit_group;" ::: "memory");
    }

    uint32_t stg = sb + K_OFF + (uint32_t)(T & 1) * KSTG2;

    // Two 64-key sub-tiles, back to back (no barrier between).
#pragma unroll
    for (int sub = 0; sub < 2; sub++) {
      uint32_t KH = stg + (uint32_t)sub * (64 * AP_ * 2);
      uint32_t KL = KH + KHALF2;

      // Phase A: S[16 x 64] per warp = Q(m16) . K^T, split 3-term.
      float S[8][4];
#pragma unroll
      for (int i = 0; i < 8; i++)
#pragma unroll
        for (int q = 0; q < 4; q++) S[i][q] = 0.0f;

#pragma unroll
      for (int g = 0; g < 8; g++) {
#pragma unroll
        for (int np = 0; np < 4; np++) {
          uint32_t bhv[4], blv[4];
          uint32_t koff = (uint32_t)((np * 16 + ((lane >> 4) << 3) + (lane & 7)) * (AP_ * 2) +
                                     (g * 16 + (((lane >> 3) & 1) << 3)) * 2);
          ldsm4(bhv, KH + koff);
          ldsm4(blv, KL + koff);
          mma_group6(S[np * 2], S[np * 2 + 1], qh[g], ql[g], bhv, blv);
        }
      }

      // Softmax numerator (p = 2^S, bounded logits) + Phase C, interleaved
      // in two independent 32-key halves.
#pragma unroll
      for (int h2 = 0; h2 < 2; h2++) {
#pragma unroll
        for (int i = 4 * h2; i < 4 * h2 + 4; i++) {
          S[i][0] = ex2f_(S[i][0]);
          S[i][1] = ex2f_(S[i][1]);
          l_a += S[i][0] + S[i][1];
          S[i][2] = ex2f_(S[i][2]);
          S[i][3] = ex2f_(S[i][3]);
          l_b += S[i][2] + S[i][3];
        }
#pragma unroll
        for (int gg = 0; gg < 2; gg++) {
          int g2 = h2 * 2 + gg;
          uint32_t pah[4], pal[4];
          trunc_split(S[2 * g2][0],     S[2 * g2][1],     pah[0], pal[0]);
          trunc_split(S[2 * g2][2],     S[2 * g2][3],     pah[1], pal[1]);
          trunc_split(S[2 * g2 + 1][0], S[2 * g2 + 1][1], pah[2], pal[2]);
          trunc_split(S[2 * g2 + 1][2], S[2 * g2 + 1][3], pah[3], pal[3]);
#pragma unroll
          for (int dp = 0; dp < 8; dp++) {
            uint32_t bhv[4], blv[4];
            uint32_t koff = (uint32_t)((g2 * 16 + (lane & 15)) * (AP_ * 2) +
                                       (dp * 16 + ((lane >> 4) << 3)) * 2);
            ldsm4t(bhv, KH + koff);
            ldsm4t(blv, KL + koff);
            mma_group6(acc[dp * 2], acc[dp * 2 + 1], pah, pal, bhv, blv);
          }
        }
      }
    }

    // Drain next-tile load and release this buffer for overwrite.
    if (T + 1 < 16) {
      asm volatile("cp.async.wait_group 0;" ::: "memory");
      __syncthreads();
    }
  }

  // Deferred l reduction (once, not per tile).
  l_a += __shfl_xor_sync(0xffffffffu, l_a, 1);
  l_a += __shfl_xor_sync(0xffffffffu, l_a, 2);
  l_b += __shfl_xor_sync(0xffffffffu, l_b, 1);
  l_b += __shfl_xor_sync(0xffffffffu, l_b, 2);

  float inva = 0.5f / l_a, invb = 0.5f / l_b;
  float* Z = (isQ ? g_Z1 : g_Z2) + (size_t)b * L_ * D_;
  int ra = r0 + w * 16 + (lane >> 2);
#pragma unroll
  for (int d = 0; d < 16; d++) {
    int col = head * DK_ + d * 8 + (lane & 3) * 2;
    float2 v0 = make_float2(acc[d][0] * inva, acc[d][1] * inva);
    float2 v1 = make_float2(acc[d][2] * invb, acc[d][3] * invb);
    *(float2*)&Z[(size_t)ra * D_ + col] = v0;
    *(float2*)&Z[(size_t)(ra + 8) * D_ + col] = v1;
  }
}

// ---------------------------------------------------------------------------
extern "C" void kernel_launch(void* const* d_in, const int* in_sizes, int n_in,
                              void* d_out, int out_size) {
  (void)in_sizes; (void)n_in; (void)out_size;
  const float* keys    = (const float*)d_in[0];
  const float* queries = (const float*)d_in[1];
  const float* values  = (const float*)d_in[2];
  const float* Wk      = (const float*)d_in[3];
  const float* Wq      = (const float*)d_in[4];
  const float* Wv      = (const float*)d_in[5];
  const float* Wu      = (const float*)d_in[6];
  const float* bu      = (const float*)d_in[7];
  float* out = (float*)d_out;

  cudaFuncSetAttribute(attn_mma, cudaFuncAttributeMaxDynamicSharedMemorySize,
                       ATTN_SMEM);
  cudaFuncSetAttribute(proj_mma2, cudaFuncAttributeMaxDynamicSharedMemorySize,
                       GEMM_SMEM);
  cudaFuncSetAttribute(final_mma2, cudaFuncAttributeMaxDynamicSharedMemorySize,
                       GEMM_SMEM);

  convert_all<<<(NCONV + 255) / 256, 256>>>(keys, queries, values, Wk, Wq, Wv, Wu);
  proj_mma2<<<dim3(16, 8, 12), 256, GEMM_SMEM>>>();
  attn_mma<<<dim3(32, 32), 256, ATTN_SMEM>>>();
  convert_zsum<<<NX4 / 256, 256>>>(NX4);
  final_mma2<<<dim3(8, 16, 4), 256, GEMM_SMEM>>>(bu, out);
}

// round 15
// speedup vs baseline: 1.0592x; 1.0059x over previous
#include <cuda_runtime.h>
#include <cuda_bf16.h>
#include <stdint.h>

// Shapes fixed by the problem: b=4, l=2048, d_model=1024, h=8, dk=128.
#define B_  4
#define L_  2048
#define D_  1024
#define H_  8
#define DK_ 128

// Pre-split inputs/weights (hi + residual lo bf16).
__device__ __nv_bfloat16 g_Xh[3 * B_ * L_ * D_];   // k/q/v inputs, [pj][b][t][d]
__device__ __nv_bfloat16 g_Xl[3 * B_ * L_ * D_];
__device__ __nv_bfloat16 g_Wh[4 * D_ * D_];        // Wk,Wq,Wv,Wu, [pj][c][d]
__device__ __nv_bfloat16 g_Wl[4 * D_ * D_];

// Projections, split bf16, channel-major Y[b][c][t]. Yq/Yv carry dk^-.5*log2e.
__device__ __nv_bfloat16 g_Ykh[B_ * D_ * L_];
__device__ __nv_bfloat16 g_Ykl[B_ * D_ * L_];
__device__ __nv_bfloat16 g_Yqh[B_ * D_ * L_];
__device__ __nv_bfloat16 g_Yql[B_ * D_ * L_];
__device__ __nv_bfloat16 g_Yvh[B_ * D_ * L_];
__device__ __nv_bfloat16 g_Yvl[B_ * D_ * L_];

// Attention output (Z1+Z2), summed in-kernel and stored as split bf16.
__device__ __nv_bfloat16 g_Zh[B_ * L_ * D_];
__device__ __nv_bfloat16 g_Zl[B_ * L_ * D_];

// ---------------------------------------------------------------------------
// Helpers
// ---------------------------------------------------------------------------
__device__ __forceinline__ uint32_t sptr(const void* p) {
  return (uint32_t)__cvta_generic_to_shared(p);
}

__device__ __forceinline__ void ldsm4(uint32_t r[4], uint32_t a) {
  asm volatile("ldmatrix.sync.aligned.m8n8.x4.shared.b16 {%0,%1,%2,%3}, [%4];"
               : "=r"(r[0]), "=r"(r[1]), "=r"(r[2]), "=r"(r[3]) : "r"(a));
}
__device__ __forceinline__ void ldsm4t(uint32_t r[4], uint32_t a) {
  asm volatile("ldmatrix.sync.aligned.m8n8.x4.trans.shared.b16 {%0,%1,%2,%3}, [%4];"
               : "=r"(r[0]), "=r"(r[1]), "=r"(r[2]), "=r"(r[3]) : "r"(a));
}

// Non-volatile on purpose: pure register op; lets ptxas interleave MMAs with
// softmax ALU/MUFU. Data dependencies preserve correctness.
__device__ __forceinline__ void mma16816(float c[4], const uint32_t a[4],
                                         uint32_t b0, uint32_t b1) {
  asm("mma.sync.aligned.m16n8k16.row.col.f32.bf16.bf16.f32 "
      "{%0,%1,%2,%3},{%4,%5,%6,%7},{%8,%9},{%0,%1,%2,%3};\n"
      : "+f"(c[0]), "+f"(c[1]), "+f"(c[2]), "+f"(c[3])
      : "r"(a[0]), "r"(a[1]), "r"(a[2]), "r"(a[3]), "r"(b0), "r"(b1));
}

// 6-MMA split group with interleaved accumulator targets (breaks RAW chains).
__device__ __forceinline__ void mma_group6(float c0[4], float c1[4],
                                           const uint32_t ah[4], const uint32_t al[4],
                                           const uint32_t bh[4], const uint32_t bl[4]) {
  mma16816(c0, ah, bh[0], bh[1]);
  mma16816(c1, ah, bh[2], bh[3]);
  mma16816(c0, ah, bl[0], bl[1]);
  mma16816(c1, ah, bl[2], bl[3]);
  mma16816(c0, al, bh[0], bh[1]);
  mma16816(c1, al, bh[2], bh[3]);
}

// Round-to-nearest split (epilogues / converts).
__device__ __forceinline__ void split_pack(float x, float y, uint32_t& h, uint32_t& l) {
  __nv_bfloat162 H = __floats2bfloat162_rn(x, y);
  float hx = __bfloat162float(H.x), hy = __bfloat162float(H.y);
  __nv_bfloat162 Lo = __floats2bfloat162_rn(x - hx, y - hy);
  h = *reinterpret_cast<uint32_t*>(&H);
  l = *reinterpret_cast<uint32_t*>(&Lo);
}

// Cheap truncation split for NON-NEGATIVE values (softmax p): 6 ops.
__device__ __forceinline__ void trunc_split(float x, float y, uint32_t& h, uint32_t& l) {
  uint32_t xb = __float_as_uint(x), yb = __float_as_uint(y);
  h = __byte_perm(xb, yb, 0x7632);
  float xl = x - __uint_as_float(xb & 0xFFFF0000u);
  float yl = y - __uint_as_float(yb & 0xFFFF0000u);
  l = __byte_perm(__float_as_uint(xl), __float_as_uint(yl), 0x7632);
}

__device__ __forceinline__ float ex2f_(float x) {
  float y;
  asm("ex2.approx.ftz.f32 %0, %1;" : "=f"(y) : "f"(x));
  return y;
}

__device__ __forceinline__ void cp16(uint32_t dst, const void* src) {
  asm volatile("cp.async.cg.shared.global [%0], [%1], 16;" :: "r"(dst), "l"(src));
}

// ---------------------------------------------------------------------------
// Kernel 0: ONE fused fp32 -> split-bf16 conversion over all 7 tensors.
// ---------------------------------------------------------------------------
#define NX4 ((B_ * L_ * D_) / 4)
#define NW4 ((D_ * D_) / 4)
#define NCONV (3 * NX4 + 4 * NW4)

__global__ void __launch_bounds__(256) convert_all(
    const float* __restrict__ k, const float* __restrict__ q,
    const float* __restrict__ v, const float* __restrict__ wk,
    const float* __restrict__ wq, const float* __restrict__ wv,
    const float* __restrict__ wu) {
  int i = blockIdx.x * 256 + threadIdx.x;
  if (i >= NCONV) return;
  const float* src;
  __nv_bfloat16 *dh, *dl;
  int local;
  if (i < 3 * NX4) {
    int which = i / NX4;
    local = i - which * NX4;
    src = (which == 0) ? k : (which == 1) ? q : v;
    dh = g_Xh + (size_t)which * (B_ * L_ * D_);
    dl = g_Xl + (size_t)which * (B_ * L_ * D_);
  } else {
    int j = i - 3 * NX4;
    int which = j / NW4;
    local = j - which * NW4;
    src = (which == 0) ? wk : (which == 1) ? wq : (which == 2) ? wv : wu;
    dh = g_Wh + (size_t)which * (D_ * D_);
    dl = g_Wl + (size_t)which * (D_ * D_);
  }
  float4 vv = reinterpret_cast<const float4*>(src)[local];
  uint32_t h0, l0, h1, l1;
  split_pack(vv.x, vv.y, h0, l0);
  split_pack(vv.z, vv.w, h1, l1);
  reinterpret_cast<uint32_t*>(dh)[local * 2]     = h0;
  reinterpret_cast<uint32_t*>(dh)[local * 2 + 1] = h1;
  reinterpret_cast<uint32_t*>(dl)[local * 2]     = l0;
  reinterpret_cast<uint32_t*>(dl)[local * 2 + 1] = l1;
}

// ---------------------------------------------------------------------------
// GEMM: 128x128 CTA tile, BK=32, pitch 40 bf16 (80 B), 2-stage cp.async ring,
// one __syncthreads per k-step. 80 KB smem -> 2 CTAs/SM (regs capped at 128).
// ---------------------------------------------------------------------------
#define GARR_B   10240                 // 128 rows * 80 B
#define GSTAGE_B (4 * GARR_B)          // 40960
#define GEMM_SMEM (2 * GSTAGE_B)       // 81920

struct GemmPtrs {
  const __nv_bfloat16 *Ah, *Al, *Bh, *Bl;
};

__device__ __forceinline__ void gemm_issue(
    const GemmPtrs& gp, uint32_t sb, int kc, int tid, int m0, int n0) {
  uint32_t stage = sb + (uint32_t)(kc & 1) * GSTAGE_B;
  int k0 = kc * 32;
  const __nv_bfloat16* ps[4] = {gp.Ah, gp.Al, gp.Bh, gp.Bl};
#pragma unroll
  for (int it = 0; it < 8; it++) {
    int f = tid + it * 256;            // 0..2047
    int arr = f >> 9, q = f & 511;     // 512 cp16 per array
    int r = q >> 2, c8 = (q & 3) * 8;  // row, bf16 col
    int row = (arr < 2 ? m0 : n0) + r;
    cp16(stage + (uint32_t)(arr * GARR_B + r * 80 + c8 * 2),
         ps[arr] + (size_t)row * D_ + k0 + c8);
  }
  asm volatile("cp.async.commit_group;" ::: "memory");
}

__device__ __forceinline__ void gemm_compute(
    float acc[2][8][4], uint32_t sb, int kc, int lane, int wm, int wn) {
  uint32_t stage = sb + (uint32_t)(kc & 1) * GSTAGE_B;
  uint32_t Ah_s = stage, Al_s = stage + GARR_B;
  uint32_t Bh_s = stage + 2 * GARR_B, Bl_s = stage + 3 * GARR_B;
#pragma unroll
  for (int g = 0; g < 2; g++) {
    uint32_t ah[2][4], al[2][4];
#pragma unroll
    for (int mi = 0; mi < 2; mi++) {
      uint32_t off = (uint32_t)((wm * 32 + mi * 16 + (lane & 15)) * 80 +
                                (g * 16 + ((lane >> 4) << 3)) * 2);
      ldsm4(ah[mi], Ah_s + off);
      ldsm4(al[mi], Al_s + off);
    }
#pragma unroll
    for (int np = 0; np < 4; np++) {
      uint32_t bhv[4], blv[4];
      uint32_t off = (uint32_t)((wn * 64 + np * 16 + ((lane >> 4) << 3) + (lane & 7)) * 80 +
                                (g * 16 + (((lane >> 3) & 1) << 3)) * 2);
      ldsm4(bhv, Bh_s + off);
      ldsm4(blv, Bl_s + off);
#pragma unroll
      for (int mi = 0; mi < 2; mi++)
        mma_group6(acc[mi][np * 2], acc[mi][np * 2 + 1], ah[mi], al[mi], bhv, blv);
    }
  }
}

// 2-stage mainloop, 32 k-steps: wait(t), bar, issue(t+1), compute(t).
__device__ __forceinline__ void gemm_mainloop(
    float acc[2][8][4], const GemmPtrs& gp, uint32_t sb, int tid, int lane,
    int wm, int wn, int m0, int n0) {
  gemm_issue(gp, sb, 0, tid, m0, n0);
  for (int t = 0; t < 32; t++) {
    asm volatile("cp.async.wait_group 0;" ::: "memory");
    __syncthreads();
    if (t + 1 < 32) gemm_issue(gp, sb, t + 1, tid, m0, n0);
    gemm_compute(acc, sb, t, lane, wm, wn);
  }
}

// ---------------------------------------------------------------------------
// Kernel 1: projections. Y[c][t] = W[c][:].X[t][:]; split-bf16 output * scl.
// ---------------------------------------------------------------------------
__global__ void __launch_bounds__(256, 2) proj_mma2() {
  extern __shared__ char smg[];
  uint32_t sb = sptr(smg);
  const float QS = 0.08838834764831845f * 1.4426950408889634f;

  int z = blockIdx.z, pj = z >> 2, b = z & 3;
  GemmPtrs gp;
  gp.Ah = g_Wh + (size_t)pj * (D_ * D_);
  gp.Al = g_Wl + (size_t)pj * (D_ * D_);
  gp.Bh = g_Xh + ((size_t)pj * B_ + b) * (L_ * D_);
  gp.Bl = g_Xl + ((size_t)pj * B_ + b) * (L_ * D_);
  __nv_bfloat16* Yh = ((pj == 0) ? g_Ykh : (pj == 1) ? g_Yqh : g_Yvh) + (size_t)b * D_ * L_;
  __nv_bfloat16* Yl = ((pj == 0) ? g_Ykl : (pj == 1) ? g_Yql : g_Yvl) + (size_t)b * D_ * L_;
  float scl = (pj == 0) ? 1.0f : QS;

  int m0 = blockIdx.y * 128, n0 = blockIdx.x * 128;
  int tid = threadIdx.x, lane = tid & 31, w = tid >> 5;
  int wm = w & 3, wn = w >> 2;

  float acc[2][8][4];
#pragma unroll
  for (int mi = 0; mi < 2; mi++)
#pragma unroll
    for (int t8 = 0; t8 < 8; t8++)
#pragma unroll
      for (int q = 0; q < 4; q++) acc[mi][t8][q] = 0.0f;

  gemm_mainloop(acc, gp, sb, tid, lane, wm, wn, m0, n0);

#pragma unroll
  for (int mi = 0; mi < 2; mi++)
#pragma unroll
    for (int t8 = 0; t8 < 8; t8++) {
      int row = m0 + wm * 32 + mi * 16 + (lane >> 2);
      int col = n0 + wn * 64 + t8 * 8 + (lane & 3) * 2;
      uint32_t h, l;
      split_pack(acc[mi][t8][0] * scl, acc[mi][t8][1] * scl, h, l);
      *(uint32_t*)&Yh[(size_t)row * L_ + col] = h;
      *(uint32_t*)&Yl[(size_t)row * L_ + col] = l;
      split_pack(acc[mi][t8][2] * scl, acc[mi][t8][3] * scl, h, l);
      *(uint32_t*)&Yh[(size_t)(row + 8) * L_ + col] = h;
      *(uint32_t*)&Yl[(size_t)(row + 8) * L_ + col] = l;
    }
}

// ---------------------------------------------------------------------------
// Kernel 3: output projection. out[t][n] = Zs[t][:].Wu[n][:] + bu[n].
// ---------------------------------------------------------------------------
__global__ void __launch_bounds__(256, 2) final_mma2(const float* __restrict__ bu,
                                                     float* __restrict__ out) {
  extern __shared__ char smg[];
  uint32_t sb = sptr(smg);

  int b = blockIdx.z;
  GemmPtrs gp;
  gp.Ah = g_Zh + (size_t)b * (L_ * D_);
  gp.Al = g_Zl + (size_t)b * (L_ * D_);
  gp.Bh = g_Wh + (size_t)3 * (D_ * D_);
  gp.Bl = g_Wl + (size_t)3 * (D_ * D_);

  int m0 = blockIdx.y * 128, n0 = blockIdx.x * 128;
  int tid = threadIdx.x, lane = tid & 31, w = tid >> 5;
  int wm = w & 3, wn = w >> 2;

  float acc[2][8][4];
#pragma unroll
  for (int mi = 0; mi < 2; mi++)
#pragma unroll
    for (int t8 = 0; t8 < 8; t8++)
#pragma unroll
      for (int q = 0; q < 4; q++) acc[mi][t8][q] = 0.0f;

  gemm_mainloop(acc, gp, sb, tid, lane, wm, wn, m0, n0);

  float* Cb = out + (size_t)b * L_ * D_;
#pragma unroll
  for (int mi = 0; mi < 2; mi++)
#pragma unroll
    for (int t8 = 0; t8 < 8; t8++) {
      int row = m0 + wm * 32 + mi * 16 + (lane >> 2);
      int col = n0 + wn * 64 + t8 * 8 + (lane & 3) * 2;
      float2 bias = *(const float2*)&bu[col];
      float2 v0 = make_float2(acc[mi][t8][0] + bias.x, acc[mi][t8][1] + bias.y);
      float2 v1 = make_float2(acc[mi][t8][2] + bias.x, acc[mi][t8][3] + bias.y);
      *(float2*)&Cb[(size_t)row * D_ + col] = v0;
      *(float2*)&Cb[(size_t)(row + 8) * D_ + col] = v1;
    }
}

// ---------------------------------------------------------------------------
// Kernel 2: fused dual flash attention, Q-path and V-path PAIRED in one CTA.
// grid (32, 32): xb -> 64 output rows r0..r0+63; m-rows 0-63 = Q-path rows,
// m-rows 64-127 = V-path rows of the SAME range (warps w and w+4 pair up).
// Epilogue combines 0.5*(acc1/l1 + acc2/l2) via smem and writes split-bf16
// g_Zh/g_Zl directly (no fp32 Z buffers, no zsum kernel).
// 2-stage ring of 128-key mega-tiles; Q fragments hoisted; no-max softmax.
// ---------------------------------------------------------------------------
#define AP_      136
#define QH_OFF   0
#define QL_OFF   (128 * AP_ * 2)
#define K_OFF    (2 * 128 * AP_ * 2)       // 69632
#define KHALF2   (128 * AP_ * 2)           // 34816 (128 rows hi or lo)
#define KSTG2    (2 * KHALF2)              // 69632 per mega-stage
#define ATTN_SMEM (K_OFF + 2 * KSTG2)      // 208896
#define RED_PITCH 132

__global__ void __launch_bounds__(256, 1) attn_mma() {
  extern __shared__ char smc[];
  uint32_t sb = sptr(smc);

  int bh = blockIdx.y, b = bh >> 3, head = bh & 7;
  int r0 = blockIdx.x * 64;              // 64 output rows per CTA

  size_t hb = (size_t)(b * D_ + head * DK_) * L_;
  const __nv_bfloat16* Yq_h = g_Yqh + hb + (size_t)r0 * DK_;
  const __nv_bfloat16* Yq_l = g_Yql + hb + (size_t)r0 * DK_;
  const __nv_bfloat16* Yv_h = g_Yvh + hb + (size_t)r0 * DK_;
  const __nv_bfloat16* Yv_l = g_Yvl + hb + (size_t)r0 * DK_;
  const __nv_bfloat16* Kh_g = g_Ykh + hb;
  const __nv_bfloat16* Kl_g = g_Ykl + hb;

  int tid = threadIdx.x, lane = tid & 31, w = tid >> 5;

  // Prologue: Q block = [rows 0-63: Yq(r0..)] [rows 64-127: Yv(r0..)], hi+lo.
#pragma unroll
  for (int it = 0; it < 16; it++) {
    int f = tid + it * 256;
    int half = f >> 11, r = (f >> 4) & 127, c = (f & 15) * 8;
    const __nv_bfloat16* base =
        (r < 64) ? (half ? Yq_l : Yq_h) : (half ? Yv_l : Yv_h);
    int rr = (r < 64) ? r : r - 64;
    cp16(sb + (half ? QL_OFF : QH_OFF) + r * (AP_ * 2) + c * 2,
         base + (size_t)rr * DK_ + c);
  }
  // K mega-stage 0 (keys 0..127, hi+lo).
#pragma unroll
  for (int it = 0; it < 16; it++) {
    int f = tid + it * 256;                // 0..4095
    int half = f >> 11, r = (f >> 4) & 127, c = (f & 15) * 8;
    cp16(sb + K_OFF + half * KHALF2 + r * (AP_ * 2) + c * 2,
         (half ? Kl_g : Kh_g) + (size_t)r * DK_ + c);
  }
  asm volatile("cp.async.commit_group;" ::: "memory");
  asm volatile("cp.async.wait_group 0;" ::: "memory");
  __syncthreads();

  // Q fragments are loop-invariant: load them once.
  uint32_t qh[8][4], ql[8][4];
#pragma unroll
  for (int g = 0; g < 8; g++) {
    uint32_t qoff = (uint32_t)((w * 16 + (lane & 15)) * (AP_ * 2) +
                               (g * 16 + ((lane >> 4) << 3)) * 2);
    ldsm4(qh[g], sb + QH_OFF + qoff);
    ldsm4(ql[g], sb + QL_OFF + qoff);
  }

  float acc[16][4];
#pragma unroll
  for (int d = 0; d < 16; d++)
#pragma unroll
    for (int q = 0; q < 4; q++) acc[d][q] = 0.0f;
  float l_a = 0.0f, l_b = 0.0f;   // lane-local partials; reduced after loop

  for (int T = 0; T < 16; T++) {
    if (T + 1 < 16) {
      uint32_t dstb = sb + K_OFF + (uint32_t)((T + 1) & 1) * KSTG2;
#pragma unroll
      for (int it = 0; it < 16; it++) {
        int f = tid + it * 256;
        int half = f >> 11, r = (f >> 4) & 127, c = (f & 15) * 8;
        cp16(dstb + half * KHALF2 + r * (AP_ * 2) + c * 2,
             (half ? Kl_g : Kh_g) + (size_t)((T + 1) * 128 + r) * DK_ + c);
      }
      asm volatile("cp.async.commit_group;" ::: "memory");
    }

    uint32_t stg = sb + K_OFF + (uint32_t)(T & 1) * KSTG2;

#pragma unroll
    for (int sub = 0; sub < 2; sub++) {
      uint32_t KH = stg + (uint32_t)sub * (64 * AP_ * 2);
      uint32_t KL = KH + KHALF2;

      // Phase A: S[16 x 64] per warp = Q(m16) . K^T, split 3-term.
      float S[8][4];
#pragma unroll
      for (int i = 0; i < 8; i++)
#pragma unroll
        for (int q = 0; q < 4; q++) S[i][q] = 0.0f;

#pragma unroll
      for (int g = 0; g < 8; g++) {
#pragma unroll
        for (int np = 0; np < 4; np++) {
          uint32_t bhv[4], blv[4];
          uint32_t koff = (uint32_t)((np * 16 + ((lane >> 4) << 3) + (lane & 7)) * (AP_ * 2) +
                                     (g * 16 + (((lane >> 3) & 1) << 3)) * 2);
          ldsm4(bhv, KH + koff);
          ldsm4(blv, KL + koff);
          mma_group6(S[np * 2], S[np * 2 + 1], qh[g], ql[g], bhv, blv);
        }
      }

      // Softmax numerator (p = 2^S, bounded logits) + Phase C, interleaved.
#pragma unroll
      for (int h2 = 0; h2 < 2; h2++) {
#pragma unroll
        for (int i = 4 * h2; i < 4 * h2 + 4; i++) {
          S[i][0] = ex2f_(S[i][0]);
          S[i][1] = ex2f_(S[i][1]);
          l_a += S[i][0] + S[i][1];
          S[i][2] = ex2f_(S[i][2]);
          S[i][3] = ex2f_(S[i][3]);
          l_b += S[i][2] + S[i][3];
        }
#pragma unroll
        for (int gg = 0; gg < 2; gg++) {
          int g2 = h2 * 2 + gg;
          uint32_t pah[4], pal[4];
          trunc_split(S[2 * g2][0],     S[2 * g2][1],     pah[0], pal[0]);
          trunc_split(S[2 * g2][2],     S[2 * g2][3],     pah[1], pal[1]);
          trunc_split(S[2 * g2 + 1][0], S[2 * g2 + 1][1], pah[2], pal[2]);
          trunc_split(S[2 * g2 + 1][2], S[2 * g2 + 1][3], pah[3], pal[3]);
#pragma unroll
          for (int dp = 0; dp < 8; dp++) {
            uint32_t bhv[4], blv[4];
            uint32_t koff = (uint32_t)((g2 * 16 + (lane & 15)) * (AP_ * 2) +
                                       (dp * 16 + ((lane >> 4) << 3)) * 2);
            ldsm4t(bhv, KH + koff);
            ldsm4t(blv, KL + koff);
            mma_group6(acc[dp * 2], acc[dp * 2 + 1], pah, pal, bhv, blv);
          }
        }
      }
    }

    if (T + 1 < 16) {
      asm volatile("cp.async.wait_group 0;" ::: "memory");
      __syncthreads();
    }
  }

  // Deferred l reduction.
  l_a += __shfl_xor_sync(0xffffffffu, l_a, 1);
  l_a += __shfl_xor_sync(0xffffffffu, l_a, 2);
  l_b += __shfl_xor_sync(0xffffffffu, l_b, 1);
  l_b += __shfl_xor_sync(0xffffffffu, l_b, 2);

  // Combine Q-path (warps 0-3) and V-path (warps 4-7) via smem; write split.
  __syncthreads();                       // all smem reads of K/Q done
  float* red = (float*)smc;              // [64 rows][RED_PITCH] fp32
  float* lred = red + 64 * RED_PITCH;    // [64]
  int ra = (w & 3) * 16 + (lane >> 2);   // paired row index 0..15 (+8)

  if (w >= 4) {
#pragma unroll
    for (int d = 0; d < 16; d++) {
      int col = d * 8 + (lane & 3) * 2;
      red[ra * RED_PITCH + col]           = acc[d][0];
      red[ra * RED_PITCH + col + 1]       = acc[d][1];
      red[(ra + 8) * RED_PITCH + col]     = acc[d][2];
      red[(ra + 8) * RED_PITCH + col + 1] = acc[d][3];
    }
    if ((lane & 3) == 0) { lred[ra] = l_a; lred[ra + 8] = l_b; }
  }
  __syncthreads();

  if (w < 4) {
    float inva1 = 0.5f / l_a, invb1 = 0.5f / l_b;
    float inva2 = 0.5f / lred[ra], invb2 = 0.5f / lred[ra + 8];
    __nv_bfloat16* Zh = g_Zh + (size_t)b * L_ * D_;
    __nv_bfloat16* Zl = g_Zl + (size_t)b * L_ * D_;
#pragma unroll
    for (int d = 0; d < 16; d++) {
      int col = d * 8 + (lane & 3) * 2;
      float z0 = acc[d][0] * inva1 + red[ra * RED_PITCH + col] * inva2;
      float z1 = acc[d][1] * inva1 + red[ra * RED_PITCH + col + 1] * inva2;
      float z2 = acc[d][2] * invb1 + red[(ra + 8) * RED_PITCH + col] * invb2;
      float z3 = acc[d][3] * invb1 + red[(ra + 8) * RED_PITCH + col + 1] * invb2;
      uint32_t h, l;
      split_pack(z0, z1, h, l);
      size_t off0 = (size_t)(r0 + ra) * D_ + head * DK_ + col;
      *(uint32_t*)&Zh[off0] = h;
      *(uint32_t*)&Zl[off0] = l;
      split_pack(z2, z3, h, l);
      size_t off1 = (size_t)(r0 + ra + 8) * D_ + head * DK_ + col;
      *(uint32_t*)&Zh[off1] = h;
      *(uint32_t*)&Zl[off1] = l;
    }
  }
}

// ---------------------------------------------------------------------------
extern "C" void kernel_launch(void* const* d_in, const int* in_sizes, int n_in,
                              void* d_out, int out_size) {
  (void)in_sizes; (void)n_in; (void)out_size;
  const float* keys    = (const float*)d_in[0];
  const float* queries = (const float*)d_in[1];
  const float* values  = (const float*)d_in[2];
  const float* Wk      = (const float*)d_in[3];
  const float* Wq      = (const float*)d_in[4];
  const float* Wv      = (const float*)d_in[5];
  const float* Wu      = (const float*)d_in[6];
  const float* bu      = (const float*)d_in[7];
  float* out = (float*)d_out;

  cudaFuncSetAttribute(attn_mma, cudaFuncAttributeMaxDynamicSharedMemorySize,
                       ATTN_SMEM);
  cudaFuncSetAttribute(proj_mma2, cudaFuncAttributeMaxDynamicSharedMemorySize,
                       GEMM_SMEM);
  cudaFuncSetAttribute(final_mma2, cudaFuncAttributeMaxDynamicSharedMemorySize,
                       GEMM_SMEM);

  convert_all<<<(NCONV + 255) / 256, 256>>>(keys, queries, values, Wk, Wq, Wv, Wu);
  proj_mma2<<<dim3(16, 8, 12), 256, GEMM_SMEM>>>();
  attn_mma<<<dim3(32, 32), 256, ATTN_SMEM>>>();
  final_mma2<<<dim3(8, 16, 4), 256, GEMM_SMEM>>>(bu, out);
}

// round 16
// speedup vs baseline: 1.0778x; 1.0176x over previous
#include <cuda_runtime.h>
#include <cuda_bf16.h>
#include <stdint.h>

// Shapes fixed by the problem: b=4, l=2048, d_model=1024, h=8, dk=128.
#define B_  4
#define L_  2048
#define D_  1024
#define H_  8
#define DK_ 128

// Pre-split inputs/weights (hi + residual lo bf16).
__device__ __nv_bfloat16 g_Xh[3 * B_ * L_ * D_];   // k/q/v inputs, [pj][b][t][d]
__device__ __nv_bfloat16 g_Xl[3 * B_ * L_ * D_];
__device__ __nv_bfloat16 g_Wh[4 * D_ * D_];        // Wk,Wq,Wv,Wu, [pj][c][d]
__device__ __nv_bfloat16 g_Wl[4 * D_ * D_];

// Projections, split bf16, channel-major Y[b][c][t]. Yq/Yv carry dk^-.5*log2e.
__device__ __nv_bfloat16 g_Ykh[B_ * D_ * L_];
__device__ __nv_bfloat16 g_Ykl[B_ * D_ * L_];
__device__ __nv_bfloat16 g_Yqh[B_ * D_ * L_];
__device__ __nv_bfloat16 g_Yql[B_ * D_ * L_];
__device__ __nv_bfloat16 g_Yvh[B_ * D_ * L_];
__device__ __nv_bfloat16 g_Yvl[B_ * D_ * L_];

// Attention output (Z1+Z2), summed in-kernel and stored as split bf16.
__device__ __nv_bfloat16 g_Zh[B_ * L_ * D_];
__device__ __nv_bfloat16 g_Zl[B_ * L_ * D_];

// ---------------------------------------------------------------------------
// Helpers
// ---------------------------------------------------------------------------
__device__ __forceinline__ uint32_t sptr(const void* p) {
  return (uint32_t)__cvta_generic_to_shared(p);
}

__device__ __forceinline__ void ldsm4(uint32_t r[4], uint32_t a) {
  asm volatile("ldmatrix.sync.aligned.m8n8.x4.shared.b16 {%0,%1,%2,%3}, [%4];"
               : "=r"(r[0]), "=r"(r[1]), "=r"(r[2]), "=r"(r[3]) : "r"(a));
}
__device__ __forceinline__ void ldsm4t(uint32_t r[4], uint32_t a) {
  asm volatile("ldmatrix.sync.aligned.m8n8.x4.trans.shared.b16 {%0,%1,%2,%3}, [%4];"
               : "=r"(r[0]), "=r"(r[1]), "=r"(r[2]), "=r"(r[3]) : "r"(a));
}

// Non-volatile on purpose: pure register op; lets ptxas interleave MMAs with
// softmax ALU/MUFU. Data dependencies preserve correctness.
__device__ __forceinline__ void mma16816(float c[4], const uint32_t a[4],
                                         uint32_t b0, uint32_t b1) {
  asm("mma.sync.aligned.m16n8k16.row.col.f32.bf16.bf16.f32 "
      "{%0,%1,%2,%3},{%4,%5,%6,%7},{%8,%9},{%0,%1,%2,%3};\n"
      : "+f"(c[0]), "+f"(c[1]), "+f"(c[2]), "+f"(c[3])
      : "r"(a[0]), "r"(a[1]), "r"(a[2]), "r"(a[3]), "r"(b0), "r"(b1));
}

// 6-MMA split group with interleaved accumulator targets (breaks RAW chains).
__device__ __forceinline__ void mma_group6(float c0[4], float c1[4],
                                           const uint32_t ah[4], const uint32_t al[4],
                                           const uint32_t bh[4], const uint32_t bl[4]) {
  mma16816(c0, ah, bh[0], bh[1]);
  mma16816(c1, ah, bh[2], bh[3]);
  mma16816(c0, ah, bl[0], bl[1]);
  mma16816(c1, ah, bl[2], bl[3]);
  mma16816(c0, al, bh[0], bh[1]);
  mma16816(c1, al, bh[2], bh[3]);
}

// Round-to-nearest split (epilogues / converts).
__device__ __forceinline__ void split_pack(float x, float y, uint32_t& h, uint32_t& l) {
  __nv_bfloat162 H = __floats2bfloat162_rn(x, y);
  float hx = __bfloat162float(H.x), hy = __bfloat162float(H.y);
  __nv_bfloat162 Lo = __floats2bfloat162_rn(x - hx, y - hy);
  h = *reinterpret_cast<uint32_t*>(&H);
  l = *reinterpret_cast<uint32_t*>(&Lo);
}

// Cheap truncation split for NON-NEGATIVE values (softmax p): 6 ops.
__device__ __forceinline__ void trunc_split(float x, float y, uint32_t& h, uint32_t& l) {
  uint32_t xb = __float_as_uint(x), yb = __float_as_uint(y);
  h = __byte_perm(xb, yb, 0x7632);
  float xl = x - __uint_as_float(xb & 0xFFFF0000u);
  float yl = y - __uint_as_float(yb & 0xFFFF0000u);
  l = __byte_perm(__float_as_uint(xl), __float_as_uint(yl), 0x7632);
}

__device__ __forceinline__ float ex2f_(float x) {
  float y;
  asm("ex2.approx.ftz.f32 %0, %1;" : "=f"(y) : "f"(x));
  return y;
}

__device__ __forceinline__ void cp16(uint32_t dst, const void* src) {
  asm volatile("cp.async.cg.shared.global [%0], [%1], 16;" :: "r"(dst), "l"(src));
}

// ---------------------------------------------------------------------------
// Kernel 0: ONE fused fp32 -> split-bf16 conversion over all 7 tensors.
// ---------------------------------------------------------------------------
#define NX4 ((B_ * L_ * D_) / 4)
#define NW4 ((D_ * D_) / 4)
#define NCONV (3 * NX4 + 4 * NW4)

__global__ void __launch_bounds__(256) convert_all(
    const float* __restrict__ k, const float* __restrict__ q,
    const float* __restrict__ v, const float* __restrict__ wk,
    const float* __restrict__ wq, const float* __restrict__ wv,
    const float* __restrict__ wu) {
  int i = blockIdx.x * 256 + threadIdx.x;
  if (i >= NCONV) return;
  const float* src;
  __nv_bfloat16 *dh, *dl;
  int local;
  if (i < 3 * NX4) {
    int which = i / NX4;
    local = i - which * NX4;
    src = (which == 0) ? k : (which == 1) ? q : v;
    dh = g_Xh + (size_t)which * (B_ * L_ * D_);
    dl = g_Xl + (size_t)which * (B_ * L_ * D_);
  } else {
    int j = i - 3 * NX4;
    int which = j / NW4;
    local = j - which * NW4;
    src = (which == 0) ? wk : (which == 1) ? wq : (which == 2) ? wv : wu;
    dh = g_Wh + (size_t)which * (D_ * D_);
    dl = g_Wl + (size_t)which * (D_ * D_);
  }
  float4 vv = reinterpret_cast<const float4*>(src)[local];
  uint32_t h0, l0, h1, l1;
  split_pack(vv.x, vv.y, h0, l0);
  split_pack(vv.z, vv.w, h1, l1);
  reinterpret_cast<uint32_t*>(dh)[local * 2]     = h0;
  reinterpret_cast<uint32_t*>(dh)[local * 2 + 1] = h1;
  reinterpret_cast<uint32_t*>(dl)[local * 2]     = l0;
  reinterpret_cast<uint32_t*>(dl)[local * 2 + 1] = l1;
}

// ---------------------------------------------------------------------------
// GEMM: 64x128 CTA tile, BK=64, pitch 72 bf16 (144 B), 2-stage cp.async ring.
// Stage = (64 A-rows + 128 B-rows) * 144 B * 2 arrays = 54 KB; 2 stages =
// 108 KB -> 2 CTAs/SM AND 16 long barrier windows (192 MMA/warp each).
// 8 warps: wm = w>>2 (2 x 32 m-rows), wn = w&3 (4 x 32 n-cols).
// ---------------------------------------------------------------------------
#define GA_B     9216                  // one A array: 64 rows * 144 B
#define GB_B     18432                 // one B array: 128 rows * 144 B
#define GAh_OFF  0
#define GAl_OFF  GA_B
#define GBh_OFF  (2 * GA_B)
#define GBl_OFF  (2 * GA_B + GB_B)
#define GSTAGE_B (2 * GA_B + 2 * GB_B) // 55296
#define GEMM_SMEM (2 * GSTAGE_B)       // 110592

struct GemmPtrs {
  const __nv_bfloat16 *Ah, *Al, *Bh, *Bl;
};

__device__ __forceinline__ void gemm_issue(
    const GemmPtrs& gp, uint32_t sb, int kc, int tid, int m0, int n0) {
  uint32_t stage = sb + (uint32_t)(kc & 1) * GSTAGE_B;
  int k0 = kc * 64;
#pragma unroll
  for (int it = 0; it < 12; it++) {
    int f = tid + it * 256;            // 0..3071
    const __nv_bfloat16* src;
    uint32_t dst;
    if (f < 1024) {                    // A: 2 arrays x 512 cp16 (64 rows x 8)
      int arr = f >> 9, qq = f & 511;
      int r = qq >> 3, c8 = (qq & 7) * 8;
      src = (arr ? gp.Al : gp.Ah) + (size_t)(m0 + r) * D_ + k0 + c8;
      dst = stage + (uint32_t)(arr ? GAl_OFF : GAh_OFF) + (uint32_t)(r * 144 + c8 * 2);
    } else {                           // B: 2 arrays x 1024 cp16 (128 rows x 8)
      int g = f - 1024;
      int arr = g >> 10, qq = g & 1023;
      int r = qq >> 3, c8 = (qq & 7) * 8;
      src = (arr ? gp.Bl : gp.Bh) + (size_t)(n0 + r) * D_ + k0 + c8;
      dst = stage + (uint32_t)(arr ? GBl_OFF : GBh_OFF) + (uint32_t)(r * 144 + c8 * 2);
    }
    cp16(dst, src);
  }
  asm volatile("cp.async.commit_group;" ::: "memory");
}

__device__ __forceinline__ void gemm_compute(
    float acc[2][4][4], uint32_t sb, int kc, int lane, int wm, int wn) {
  uint32_t stage = sb + (uint32_t)(kc & 1) * GSTAGE_B;
  uint32_t Ah_s = stage + GAh_OFF, Al_s = stage + GAl_OFF;
  uint32_t Bh_s = stage + GBh_OFF, Bl_s = stage + GBl_OFF;
#pragma unroll
  for (int g = 0; g < 4; g++) {        // 4 k16 groups (BK=64)
    uint32_t ah[2][4], al[2][4];
#pragma unroll
    for (int mi = 0; mi < 2; mi++) {
      uint32_t off = (uint32_t)((wm * 32 + mi * 16 + (lane & 15)) * 144 +
                                (g * 16 + ((lane >> 4) << 3)) * 2);
      ldsm4(ah[mi], Ah_s + off);
      ldsm4(al[mi], Al_s + off);
    }
#pragma unroll
    for (int np = 0; np < 2; np++) {
      uint32_t bhv[4], blv[4];
      uint32_t off = (uint32_t)((wn * 32 + np * 16 + ((lane >> 4) << 3) + (lane & 7)) * 144 +
                                (g * 16 + (((lane >> 3) & 1) << 3)) * 2);
      ldsm4(bhv, Bh_s + off);
      ldsm4(blv, Bl_s + off);
#pragma unroll
      for (int mi = 0; mi < 2; mi++)
        mma_group6(acc[mi][np * 2], acc[mi][np * 2 + 1], ah[mi], al[mi], bhv, blv);
    }
  }
}

// 2-stage mainloop, 16 k-windows: wait(t), bar, issue(t+1), compute(t).
__device__ __forceinline__ void gemm_mainloop(
    float acc[2][4][4], const GemmPtrs& gp, uint32_t sb, int tid, int lane,
    int wm, int wn, int m0, int n0) {
  gemm_issue(gp, sb, 0, tid, m0, n0);
  for (int t = 0; t < 16; t++) {
    asm volatile("cp.async.wait_group 0;" ::: "memory");
    __syncthreads();
    if (t + 1 < 16) gemm_issue(gp, sb, t + 1, tid, m0, n0);
    gemm_compute(acc, sb, t, lane, wm, wn);
  }
}

// ---------------------------------------------------------------------------
// Kernel 1: projections. Y[c][t] = W[c][:].X[t][:]; split-bf16 output * scl.
// Grid: x = t-tiles (L/128 = 16), y = c-tiles (D/64 = 16), z = pj*4+b.
// ---------------------------------------------------------------------------
__global__ void __launch_bounds__(256, 2) proj_mma2() {
  extern __shared__ char smg[];
  uint32_t sb = sptr(smg);
  const float QS = 0.08838834764831845f * 1.4426950408889634f;

  int z = blockIdx.z, pj = z >> 2, b = z & 3;
  GemmPtrs gp;
  gp.Ah = g_Wh + (size_t)pj * (D_ * D_);
  gp.Al = g_Wl + (size_t)pj * (D_ * D_);
  gp.Bh = g_Xh + ((size_t)pj * B_ + b) * (L_ * D_);
  gp.Bl = g_Xl + ((size_t)pj * B_ + b) * (L_ * D_);
  __nv_bfloat16* Yh = ((pj == 0) ? g_Ykh : (pj == 1) ? g_Yqh : g_Yvh) + (size_t)b * D_ * L_;
  __nv_bfloat16* Yl = ((pj == 0) ? g_Ykl : (pj == 1) ? g_Yql : g_Yvl) + (size_t)b * D_ * L_;
  float scl = (pj == 0) ? 1.0f : QS;

  int m0 = blockIdx.y * 64, n0 = blockIdx.x * 128;
  int tid = threadIdx.x, lane = tid & 31, w = tid >> 5;
  int wm = w >> 2, wn = w & 3;

  float acc[2][4][4];
#pragma unroll
  for (int mi = 0; mi < 2; mi++)
#pragma unroll
    for (int t4 = 0; t4 < 4; t4++)
#pragma unroll
      for (int q = 0; q < 4; q++) acc[mi][t4][q] = 0.0f;

  gemm_mainloop(acc, gp, sb, tid, lane, wm, wn, m0, n0);

#pragma unroll
  for (int mi = 0; mi < 2; mi++)
#pragma unroll
    for (int t4 = 0; t4 < 4; t4++) {
      int row = m0 + wm * 32 + mi * 16 + (lane >> 2);
      int col = n0 + wn * 32 + t4 * 8 + (lane & 3) * 2;
      uint32_t h, l;
      split_pack(acc[mi][t4][0] * scl, acc[mi][t4][1] * scl, h, l);
      *(uint32_t*)&Yh[(size_t)row * L_ + col] = h;
      *(uint32_t*)&Yl[(size_t)row * L_ + col] = l;
      split_pack(acc[mi][t4][2] * scl, acc[mi][t4][3] * scl, h, l);
      *(uint32_t*)&Yh[(size_t)(row + 8) * L_ + col] = h;
      *(uint32_t*)&Yl[(size_t)(row + 8) * L_ + col] = l;
    }
}

// ---------------------------------------------------------------------------
// Kernel 3: output projection. out[t][n] = Zs[t][:].Wu[n][:] + bu[n].
// Grid: x = n-tiles (D/128 = 8), y = t-tiles (L/64 = 32), z = b.
// ---------------------------------------------------------------------------
__global__ void __launch_bounds__(256, 2) final_mma2(const float* __restrict__ bu,
                                                     float* __restrict__ out) {
  extern __shared__ char smg[];
  uint32_t sb = sptr(smg);

  int b = blockIdx.z;
  GemmPtrs gp;
  gp.Ah = g_Zh + (size_t)b * (L_ * D_);
  gp.Al = g_Zl + (size_t)b * (L_ * D_);
  gp.Bh = g_Wh + (size_t)3 * (D_ * D_);
  gp.Bl = g_Wl + (size_t)3 * (D_ * D_);

  int m0 = blockIdx.y * 64, n0 = blockIdx.x * 128;
  int tid = threadIdx.x, lane = tid & 31, w = tid >> 5;
  int wm = w >> 2, wn = w & 3;

  float acc[2][4][4];
#pragma unroll
  for (int mi = 0; mi < 2; mi++)
#pragma unroll
    for (int t4 = 0; t4 < 4; t4++)
#pragma unroll
      for (int q = 0; q < 4; q++) acc[mi][t4][q] = 0.0f;

  gemm_mainloop(acc, gp, sb, tid, lane, wm, wn, m0, n0);

  float* Cb = out + (size_t)b * L_ * D_;
#pragma unroll
  for (int mi = 0; mi < 2; mi++)
#pragma unroll
    for (int t4 = 0; t4 < 4; t4++) {
      int row = m0 + wm * 32 + mi * 16 + (lane >> 2);
      int col = n0 + wn * 32 + t4 * 8 + (lane & 3) * 2;
      float2 bias = *(const float2*)&bu[col];
      float2 v0 = make_float2(acc[mi][t4][0] + bias.x, acc[mi][t4][1] + bias.y);
      float2 v1 = make_float2(acc[mi][t4][2] + bias.x, acc[mi][t4][3] + bias.y);
      *(float2*)&Cb[(size_t)row * D_ + col] = v0;
      *(float2*)&Cb[(size_t)(row + 8) * D_ + col] = v1;
    }
}

// ---------------------------------------------------------------------------
// Kernel 2: fused dual flash attention, Q-path and V-path PAIRED in one CTA
// (unchanged from R15). 2-stage ring of 128-key mega-tiles; Q fragments
// hoisted; no-max softmax; epilogue combines 0.5*(acc1/l1 + acc2/l2) and
// writes split-bf16 g_Zh/g_Zl directly.
// ---------------------------------------------------------------------------
#define AP_      136
#define QH_OFF   0
#define QL_OFF   (128 * AP_ * 2)
#define K_OFF    (2 * 128 * AP_ * 2)       // 69632
#define KHALF2   (128 * AP_ * 2)           // 34816 (128 rows hi or lo)
#define KSTG2    (2 * KHALF2)              // 69632 per mega-stage
#define ATTN_SMEM (K_OFF + 2 * KSTG2)      // 208896
#define RED_PITCH 132

__global__ void __launch_bounds__(256, 1) attn_mma() {
  extern __shared__ char smc[];
  uint32_t sb = sptr(smc);

  int bh = blockIdx.y, b = bh >> 3, head = bh & 7;
  int r0 = blockIdx.x * 64;              // 64 output rows per CTA

  size_t hb = (size_t)(b * D_ + head * DK_) * L_;
  const __nv_bfloat16* Yq_h = g_Yqh + hb + (size_t)r0 * DK_;
  const __nv_bfloat16* Yq_l = g_Yql + hb + (size_t)r0 * DK_;
  const __nv_bfloat16* Yv_h = g_Yvh + hb + (size_t)r0 * DK_;
  const __nv_bfloat16* Yv_l = g_Yvl + hb + (size_t)r0 * DK_;
  const __nv_bfloat16* Kh_g = g_Ykh + hb;
  const __nv_bfloat16* Kl_g = g_Ykl + hb;

  int tid = threadIdx.x, lane = tid & 31, w = tid >> 5;

  // Prologue: Q block = [rows 0-63: Yq(r0..)] [rows 64-127: Yv(r0..)], hi+lo.
#pragma unroll
  for (int it = 0; it < 16; it++) {
    int f = tid + it * 256;
    int half = f >> 11, r = (f >> 4) & 127, c = (f & 15) * 8;
    const __nv_bfloat16* base =
        (r < 64) ? (half ? Yq_l : Yq_h) : (half ? Yv_l : Yv_h);
    int rr = (r < 64) ? r : r - 64;
    cp16(sb + (half ? QL_OFF : QH_OFF) + r * (AP_ * 2) + c * 2,
         base + (size_t)rr * DK_ + c);
  }
  // K mega-stage 0 (keys 0..127, hi+lo).
#pragma unroll
  for (int it = 0; it < 16; it++) {
    int f = tid + it * 256;                // 0..4095
    int half = f >> 11, r = (f >> 4) & 127, c = (f & 15) * 8;
    cp16(sb + K_OFF + half * KHALF2 + r * (AP_ * 2) + c * 2,
         (half ? Kl_g : Kh_g) + (size_t)r * DK_ + c);
  }
  asm volatile("cp.async.commit_group;" ::: "memory");
  asm volatile("cp.async.wait_group 0;" ::: "memory");
  __syncthreads();

  // Q fragments are loop-invariant: load them once.
  uint32_t qh[8][4], ql[8][4];
#pragma unroll
  for (int g = 0; g < 8; g++) {
    uint32_t qoff = (uint32_t)((w * 16 + (lane & 15)) * (AP_ * 2) +
                               (g * 16 + ((lane >> 4) << 3)) * 2);
    ldsm4(qh[g], sb + QH_OFF + qoff);
    ldsm4(ql[g], sb + QL_OFF + qoff);
  }

  float acc[16][4];
#pragma unroll
  for (int d = 0; d < 16; d++)
#pragma unroll
    for (int q = 0; q < 4; q++) acc[d][q] = 0.0f;
  float l_a = 0.0f, l_b = 0.0f;   // lane-local partials; reduced after loop

  for (int T = 0; T < 16; T++) {
    if (T + 1 < 16) {
      uint32_t dstb = sb + K_OFF + (uint32_t)((T + 1) & 1) * KSTG2;
#pragma unroll
      for (int it = 0; it < 16; it++) {
        int f = tid + it * 256;
        int half = f >> 11, r = (f >> 4) & 127, c = (f & 15) * 8;
        cp16(dstb + half * KHALF2 + r * (AP_ * 2) + c * 2,
             (half ? Kl_g : Kh_g) + (size_t)((T + 1) * 128 + r) * DK_ + c);
      }
      asm volatile("cp.async.commit_group;" ::: "memory");
    }

    uint32_t stg = sb + K_OFF + (uint32_t)(T & 1) * KSTG2;

#pragma unroll
    for (int sub = 0; sub < 2; sub++) {
      uint32_t KH = stg + (uint32_t)sub * (64 * AP_ * 2);
      uint32_t KL = KH + KHALF2;

      // Phase A: S[16 x 64] per warp = Q(m16) . K^T, split 3-term.
      float S[8][4];
#pragma unroll
      for (int i = 0; i < 8; i++)
#pragma unroll
        for (int q = 0; q < 4; q++) S[i][q] = 0.0f;

#pragma unroll
      for (int g = 0; g < 8; g++) {
#pragma unroll
        for (int np = 0; np < 4; np++) {
          uint32_t bhv[4], blv[4];
          uint32_t koff = (uint32_t)((np * 16 + ((lane >> 4) << 3) + (lane & 7)) * (AP_ * 2) +
                                     (g * 16 + (((lane >> 3) & 1) << 3)) * 2);
          ldsm4(bhv, KH + koff);
          ldsm4(blv, KL + koff);
          mma_group6(S[np * 2], S[np * 2 + 1], qh[g], ql[g], bhv, blv);
        }
      }

      // Softmax numerator (p = 2^S, bounded logits) + Phase C, interleaved.
#pragma unroll
      for (int h2 = 0; h2 < 2; h2++) {
#pragma unroll
        for (int i = 4 * h2; i < 4 * h2 + 4; i++) {
          S[i][0] = ex2f_(S[i][0]);
          S[i][1] = ex2f_(S[i][1]);
          l_a += S[i][0] + S[i][1];
          S[i][2] = ex2f_(S[i][2]);
          S[i][3] = ex2f_(S[i][3]);
          l_b += S[i][2] + S[i][3];
        }
#pragma unroll
        for (int gg = 0; gg < 2; gg++) {
          int g2 = h2 * 2 + gg;
          uint32_t pah[4], pal[4];
          trunc_split(S[2 * g2][0],     S[2 * g2][1],     pah[0], pal[0]);
          trunc_split(S[2 * g2][2],     S[2 * g2][3],     pah[1], pal[1]);
          trunc_split(S[2 * g2 + 1][0], S[2 * g2 + 1][1], pah[2], pal[2]);
          trunc_split(S[2 * g2 + 1][2], S[2 * g2 + 1][3], pah[3], pal[3]);
#pragma unroll
          for (int dp = 0; dp < 8; dp++) {
            uint32_t bhv[4], blv[4];
            uint32_t koff = (uint32_t)((g2 * 16 + (lane & 15)) * (AP_ * 2) +
                                       (dp * 16 + ((lane >> 4) << 3)) * 2);
            ldsm4t(bhv, KH + koff);
            ldsm4t(blv, KL + koff);
            mma_group6(acc[dp * 2], acc[dp * 2 + 1], pah, pal, bhv, blv);
          }
        }
      }
    }

    if (T + 1 < 16) {
      asm volatile("cp.async.wait_group 0;" ::: "memory");
      __syncthreads();
    }
  }

  // Deferred l reduction.
  l_a += __shfl_xor_sync(0xffffffffu, l_a, 1);
  l_a += __shfl_xor_sync(0xffffffffu, l_a, 2);
  l_b += __shfl_xor_sync(0xffffffffu, l_b, 1);
  l_b += __shfl_xor_sync(0xffffffffu, l_b, 2);

  // Combine Q-path (warps 0-3) and V-path (warps 4-7) via smem; write split.
  __syncthreads();                       // all smem reads of K/Q done
  float* red = (float*)smc;              // [64 rows][RED_PITCH] fp32
  float* lred = red + 64 * RED_PITCH;    // [64]
  int ra = (w & 3) * 16 + (lane >> 2);   // paired row index 0..15 (+8)

  if (w >= 4) {
#pragma unroll
    for (int d = 0; d < 16; d++) {
      int col = d * 8 + (lane & 3) * 2;
      red[ra * RED_PITCH + col]           = acc[d][0];
      red[ra * RED_PITCH + col + 1]       = acc[d][1];
      red[(ra + 8) * RED_PITCH + col]     = acc[d][2];
      red[(ra + 8) * RED_PITCH + col + 1] = acc[d][3];
    }
    if ((lane & 3) == 0) { lred[ra] = l_a; lred[ra + 8] = l_b; }
  }
  __syncthreads();

  if (w < 4) {
    float inva1 = 0.5f / l_a, invb1 = 0.5f / l_b;
    float inva2 = 0.5f / lred[ra], invb2 = 0.5f / lred[ra + 8];
    __nv_bfloat16* Zh = g_Zh + (size_t)b * L_ * D_;
    __nv_bfloat16* Zl = g_Zl + (size_t)b * L_ * D_;
#pragma unroll
    for (int d = 0; d < 16; d++) {
      int col = d * 8 + (lane & 3) * 2;
      float z0 = acc[d][0] * inva1 + red[ra * RED_PITCH + col] * inva2;
      float z1 = acc[d][1] * inva1 + red[ra * RED_PITCH + col + 1] * inva2;
      float z2 = acc[d][2] * invb1 + red[(ra + 8) * RED_PITCH + col] * invb2;
      float z3 = acc[d][3] * invb1 + red[(ra + 8) * RED_PITCH + col + 1] * invb2;
      uint32_t h, l;
      split_pack(z0, z1, h, l);
      size_t off0 = (size_t)(r0 + ra) * D_ + head * DK_ + col;
      *(uint32_t*)&Zh[off0] = h;
      *(uint32_t*)&Zl[off0] = l;
      split_pack(z2, z3, h, l);
      size_t off1 = (size_t)(r0 + ra + 8) * D_ + head * DK_ + col;
      *(uint32_t*)&Zh[off1] = h;
      *(uint32_t*)&Zl[off1] = l;
    }
  }
}

// ---------------------------------------------------------------------------
extern "C" void kernel_launch(void* const* d_in, const int* in_sizes, int n_in,
                              void* d_out, int out_size) {
  (void)in_sizes; (void)n_in; (void)out_size;
  const float* keys    = (const float*)d_in[0];
  const float* queries = (const float*)d_in[1];
  const float* values  = (const float*)d_in[2];
  const float* Wk      = (const float*)d_in[3];
  const float* Wq      = (const float*)d_in[4];
  const float* Wv      = (const float*)d_in[5];
  const float* Wu      = (const float*)d_in[6];
  const float* bu      = (const float*)d_in[7];
  float* out = (float*)d_out;

  cudaFuncSetAttribute(attn_mma, cudaFuncAttributeMaxDynamicSharedMemorySize,
                       ATTN_SMEM);
  cudaFuncSetAttribute(proj_mma2, cudaFuncAttributeMaxDynamicSharedMemorySize,
                       GEMM_SMEM);
  cudaFuncSetAttribute(final_mma2, cudaFuncAttributeMaxDynamicSharedMemorySize,
                       GEMM_SMEM);

  convert_all<<<(NCONV + 255) / 256, 256>>>(keys, queries, values, Wk, Wq, Wv, Wu);
  proj_mma2<<<dim3(16, 16, 12), 256, GEMM_SMEM>>>();
  attn_mma<<<dim3(32, 32), 256, ATTN_SMEM>>>();
  final_mma2<<<dim3(8, 32, 4), 256, GEMM_SMEM>>>(bu, out);
}